// round 2
// baseline (speedup 1.0000x reference)
#include <cuda_runtime.h>
#include <math.h>

// Problem constants
#define BATCH 2
#define SEQ   2048
#define DIM   1024
#define HEADS 16
#define HD    64
#define QKVD  3072   // 3*DIM

// Scratch (alloc-free rule: __device__ globals)
__device__ float g_qkv [(size_t)BATCH * SEQ * QKVD];   // [B, N, 3D]
__device__ float g_aout[(size_t)BATCH * SEQ * DIM];    // [B, N, D]

// ---------------------------------------------------------------------------
// SGEMM:  C[M,N] = A[M,K] @ B[N,K]^T + bias[N]
// 128x128 tile, BK=8, 256 threads, 8x8 microtile per thread.
// ---------------------------------------------------------------------------
#define BM 128
#define BN 128
#define BKK 8
#define SPAD 4

__global__ __launch_bounds__(256) void sgemm_nt_bias(
    int M, int N, int K,
    const float* __restrict__ A,    // [M,K]
    const float* __restrict__ B,    // [N,K]
    const float* __restrict__ bias, // [N]
    float* __restrict__ C)          // [M,N]
{
    __shared__ float As[BKK][BM + SPAD];
    __shared__ float Bs[BKK][BN + SPAD];

    const int t  = threadIdx.x;
    const int m0 = blockIdx.y * BM;
    const int n0 = blockIdx.x * BN;
    const int lr = t >> 1;          // 0..127: row within tile for loading
    const int lk = (t & 1) * 4;     // 0 or 4: k offset for loading
    const int tx = t & 15;          // n-direction microtile
    const int ty = t >> 4;          // m-direction microtile

    float acc[8][8];
#pragma unroll
    for (int i = 0; i < 8; i++)
#pragma unroll
        for (int j = 0; j < 8; j++) acc[i][j] = 0.0f;

    const float* Aptr = A + (size_t)(m0 + lr) * K + lk;
    const float* Bptr = B + (size_t)(n0 + lr) * K + lk;

    for (int k0 = 0; k0 < K; k0 += BKK) {
        float4 av = *(const float4*)(Aptr + k0);
        float4 bv = *(const float4*)(Bptr + k0);
        As[lk + 0][lr] = av.x; As[lk + 1][lr] = av.y;
        As[lk + 2][lr] = av.z; As[lk + 3][lr] = av.w;
        Bs[lk + 0][lr] = bv.x; Bs[lk + 1][lr] = bv.y;
        Bs[lk + 2][lr] = bv.z; Bs[lk + 3][lr] = bv.w;
        __syncthreads();

#pragma unroll
        for (int kk = 0; kk < BKK; kk++) {
            float ra[8], rb[8];
            *(float4*)(ra)     = *(const float4*)&As[kk][ty * 8];
            *(float4*)(ra + 4) = *(const float4*)&As[kk][ty * 8 + 4];
            *(float4*)(rb)     = *(const float4*)&Bs[kk][tx * 8];
            *(float4*)(rb + 4) = *(const float4*)&Bs[kk][tx * 8 + 4];
#pragma unroll
            for (int i = 0; i < 8; i++)
#pragma unroll
                for (int j = 0; j < 8; j++)
                    acc[i][j] = fmaf(ra[i], rb[j], acc[i][j]);
        }
        __syncthreads();
    }

    // Epilogue: add bias, store
#pragma unroll
    for (int i = 0; i < 8; i++) {
        const int row = m0 + ty * 8 + i;
        float* crow = C + (size_t)row * N + n0 + tx * 8;
#pragma unroll
        for (int j4 = 0; j4 < 2; j4++) {
            const int cb = tx * 8 + j4 * 4;
            float4 o;
            o.x = acc[i][j4 * 4 + 0] + bias[n0 + cb + 0];
            o.y = acc[i][j4 * 4 + 1] + bias[n0 + cb + 1];
            o.z = acc[i][j4 * 4 + 2] + bias[n0 + cb + 2];
            o.w = acc[i][j4 * 4 + 3] + bias[n0 + cb + 3];
            *(float4*)(crow + j4 * 4) = o;
        }
    }
}

// ---------------------------------------------------------------------------
// Flash attention (causal): grid (N/64, H, B), 256 threads.
// 64 q-rows per block; group of 4 threads per q-row, each owns 16 dims.
// K/V tiles of 64 keys staged in shared memory; online softmax.
// Causality applied as a DATA mask — control flow is block-uniform so the
// group shuffles are safe.
// ---------------------------------------------------------------------------
__global__ __launch_bounds__(256) void attn_kernel(
    const float* __restrict__ qkv,  // [B, N, 3D]
    float* __restrict__ aout)       // [B, N, D]
{
    const int qt = blockIdx.x;
    const int h  = blockIdx.y;
    const int b  = blockIdx.z;
    const int tid = threadIdx.x;
    const int g = tid >> 2;   // q row within tile (0..63)
    const int l = tid & 3;    // dim group (0..3), owns dims [l*16, l*16+16)
    const int qi = qt * 64 + g;

    __shared__ float Ks[64][64];
    __shared__ float Vs[64][64];

    const float* base = qkv + (size_t)b * SEQ * QKVD;

    // Load this thread's 16-dim slice of its q row
    float qreg[16];
    {
        const float* qrow = base + (size_t)qi * QKVD + h * HD + l * 16;
#pragma unroll
        for (int d4 = 0; d4 < 4; d4++) {
            float4 v = *(const float4*)(qrow + d4 * 4);
            qreg[d4 * 4 + 0] = v.x; qreg[d4 * 4 + 1] = v.y;
            qreg[d4 * 4 + 2] = v.z; qreg[d4 * 4 + 3] = v.w;
        }
    }

    float m = -1e30f, lsum = 0.0f;
    float o[16];
#pragma unroll
    for (int d = 0; d < 16; d++) o[d] = 0.0f;

    const float scale = 0.125f;  // 1/sqrt(64)
    const int ntiles = qt + 1;

    for (int kt = 0; kt < ntiles; kt++) {
        const int kbase = kt * 64;
        // Cooperative load of K and V tiles (64 keys x 64 dims)
        for (int i = tid; i < 64 * 16; i += 256) {
            const int r = i >> 4;
            const int c = (i & 15) * 4;
            const float* src = base + (size_t)(kbase + r) * QKVD + h * HD + c;
            *(float4*)&Ks[r][c] = *(const float4*)(src + DIM);
            *(float4*)&Vs[r][c] = *(const float4*)(src + 2 * DIM);
        }
        __syncthreads();

        // Block-uniform trip count; causality is a data mask.
        for (int j = 0; j < 64; j++) {
            // partial dot over my 16 dims
            float s = 0.0f;
            const float* krow = &Ks[j][l * 16];
#pragma unroll
            for (int d = 0; d < 16; d++) s = fmaf(qreg[d], krow[d], s);
            // reduce across the 4-lane group (uniform control flow)
            s += __shfl_xor_sync(0xffffffffu, s, 1);
            s += __shfl_xor_sync(0xffffffffu, s, 2);
            s *= scale;
            // causal mask: key index kbase+j must be <= qi
            s = (kbase + j <= qi) ? s : -1e30f;

            const float nm   = fmaxf(m, s);
            const float corr = __expf(m - nm);
            const float p    = __expf(s - nm);
            lsum = lsum * corr + p;
            const float* vrow = &Vs[j][l * 16];
#pragma unroll
            for (int d = 0; d < 16; d++)
                o[d] = fmaf(o[d], corr, p * vrow[d]);
            m = nm;
        }
        __syncthreads();
    }

    const float inv = 1.0f / lsum;
    float* orow = aout + ((size_t)b * SEQ + qi) * DIM + h * HD + l * 16;
#pragma unroll
    for (int d4 = 0; d4 < 4; d4++) {
        float4 v;
        v.x = o[d4 * 4 + 0] * inv; v.y = o[d4 * 4 + 1] * inv;
        v.z = o[d4 * 4 + 2] * inv; v.w = o[d4 * 4 + 3] * inv;
        *(float4*)(orow + d4 * 4) = v;
    }
}

// ---------------------------------------------------------------------------
extern "C" void kernel_launch(void* const* d_in, const int* in_sizes, int n_in,
                              void* d_out, int out_size)
{
    const float* x     = (const float*)d_in[0];   // [B,N,D]
    const float* W_qkv = (const float*)d_in[1];   // [3D,D]
    const float* b_qkv = (const float*)d_in[2];   // [3D]
    const float* W_out = (const float*)d_in[3];   // [D,D]
    const float* b_out = (const float*)d_in[4];   // [D]
    float* out = (float*)d_out;                   // [B,N,D]

    float* qkv  = nullptr;
    float* aout = nullptr;
    cudaGetSymbolAddress((void**)&qkv,  g_qkv);
    cudaGetSymbolAddress((void**)&aout, g_aout);

    const int M = BATCH * SEQ;  // 4096

    // 1) QKV projection: [4096,3072] = x[4096,1024] @ W_qkv[3072,1024]^T + b
    {
        dim3 grid(QKVD / BN, M / BM);
        sgemm_nt_bias<<<grid, 256>>>(M, QKVD, DIM, x, W_qkv, b_qkv, qkv);
    }

    // 2) Causal flash attention
    {
        dim3 grid(SEQ / 64, HEADS, BATCH);
        attn_kernel<<<grid, 256>>>(qkv, aout);
    }

    // 3) Output projection: [4096,1024] = aout @ W_out[1024,1024]^T + b
    {
        dim3 grid(DIM / BN, M / BM);
        sgemm_nt_bias<<<grid, 256>>>(M, DIM, DIM, aout, W_out, b_out, out);
    }
}

// round 3
// speedup vs baseline: 1.8657x; 1.8657x over previous
#include <cuda_runtime.h>
#include <math.h>

// Problem constants
#define BATCH 2
#define SEQ   2048
#define DIM   1024
#define HEADS 16
#define HD    64
#define QKVD  3072   // 3*DIM

// Scratch (alloc-free rule: __device__ globals)
__device__ float g_qkv [(size_t)BATCH * SEQ * QKVD];   // [B, N, 3D]
__device__ float g_aout[(size_t)BATCH * SEQ * DIM];    // [B, N, D]

// ---------------------------------------------------------------------------
// SGEMM:  C[M,N] = A[M,K] @ B[N,K]^T + bias[N]   (unchanged from R2)
// ---------------------------------------------------------------------------
#define BM 128
#define BN 128
#define BKK 8
#define SPAD 4

__global__ __launch_bounds__(256) void sgemm_nt_bias(
    int M, int N, int K,
    const float* __restrict__ A,
    const float* __restrict__ B,
    const float* __restrict__ bias,
    float* __restrict__ C)
{
    __shared__ float As[BKK][BM + SPAD];
    __shared__ float Bs[BKK][BN + SPAD];

    const int t  = threadIdx.x;
    const int m0 = blockIdx.y * BM;
    const int n0 = blockIdx.x * BN;
    const int lr = t >> 1;
    const int lk = (t & 1) * 4;
    const int tx = t & 15;
    const int ty = t >> 4;

    float acc[8][8];
#pragma unroll
    for (int i = 0; i < 8; i++)
#pragma unroll
        for (int j = 0; j < 8; j++) acc[i][j] = 0.0f;

    const float* Aptr = A + (size_t)(m0 + lr) * K + lk;
    const float* Bptr = B + (size_t)(n0 + lr) * K + lk;

    for (int k0 = 0; k0 < K; k0 += BKK) {
        float4 av = *(const float4*)(Aptr + k0);
        float4 bv = *(const float4*)(Bptr + k0);
        As[lk + 0][lr] = av.x; As[lk + 1][lr] = av.y;
        As[lk + 2][lr] = av.z; As[lk + 3][lr] = av.w;
        Bs[lk + 0][lr] = bv.x; Bs[lk + 1][lr] = bv.y;
        Bs[lk + 2][lr] = bv.z; Bs[lk + 3][lr] = bv.w;
        __syncthreads();

#pragma unroll
        for (int kk = 0; kk < BKK; kk++) {
            float ra[8], rb[8];
            *(float4*)(ra)     = *(const float4*)&As[kk][ty * 8];
            *(float4*)(ra + 4) = *(const float4*)&As[kk][ty * 8 + 4];
            *(float4*)(rb)     = *(const float4*)&Bs[kk][tx * 8];
            *(float4*)(rb + 4) = *(const float4*)&Bs[kk][tx * 8 + 4];
#pragma unroll
            for (int i = 0; i < 8; i++)
#pragma unroll
                for (int j = 0; j < 8; j++)
                    acc[i][j] = fmaf(ra[i], rb[j], acc[i][j]);
        }
        __syncthreads();
    }

#pragma unroll
    for (int i = 0; i < 8; i++) {
        const int row = m0 + ty * 8 + i;
        float* crow = C + (size_t)row * N + n0 + tx * 8;
#pragma unroll
        for (int j4 = 0; j4 < 2; j4++) {
            const int cb = tx * 8 + j4 * 4;
            float4 o;
            o.x = acc[i][j4 * 4 + 0] + bias[n0 + cb + 0];
            o.y = acc[i][j4 * 4 + 1] + bias[n0 + cb + 1];
            o.z = acc[i][j4 * 4 + 2] + bias[n0 + cb + 2];
            o.w = acc[i][j4 * 4 + 3] + bias[n0 + cb + 3];
            *(float4*)(crow + j4 * 4) = o;
        }
    }
}

// ---------------------------------------------------------------------------
// Flash attention v2-style (causal), register-tiled two-GEMM formulation.
// Block: 128 q-rows x 1 head. 256 threads: ty=tid>>4 (8 rows), tx=tid&15
// (4 cols of S / 4 dims of O). K-tiles of 64 keys.
// Dynamic smem layout (floats):
//   Qs [64][129]  Q transposed  (Qs[d][r])     8256
//   Ks [64][65]   K transposed  (Ks[d][c])     4160
//   Vs [64][64]   V natural     (Vs[k][dd])    4096
//   Ps [64][128]  P             (Ps[k][r])     8192
// ---------------------------------------------------------------------------
#define BQ  128
#define BKEY 64
#define QS_W 129
#define KS_W 65
#define ATTN_SMEM_BYTES ((64*129 + 64*65 + 64*64 + 64*128) * 4)

__global__ __launch_bounds__(256) void attn_kernel(
    const float* __restrict__ qkv,  // [B, N, 3D]
    float* __restrict__ aout)       // [B, N, D]
{
    extern __shared__ float sm[];
    float* Qs = sm;                        // [64][129]
    float* Ks = Qs + 64 * QS_W;            // [64][65]
    float* Vs = Ks + 64 * KS_W;            // [64][64]
    float* Ps = Vs + 64 * 64;              // [64][128]

    // Heaviest q-tiles first (tail-balance)
    const int qt = gridDim.x - 1 - blockIdx.x;
    const int h  = blockIdx.y;
    const int b  = blockIdx.z;
    const int tid = threadIdx.x;
    const int tx = tid & 15;
    const int ty = tid >> 4;
    const int r0 = ty * 8;
    const int c0 = tx * 4;

    const float* base = qkv + (size_t)b * SEQ * QKVD + h * HD;

    // ---- Load Q tile transposed: Qs[d][r] ----
    {
        const int r  = tid >> 1;          // 0..127
        const int d0 = (tid & 1) * 32;    // 0 or 32
        const float* qrow = base + (size_t)(qt * BQ + r) * QKVD + d0;
#pragma unroll
        for (int d4 = 0; d4 < 8; d4++) {
            float4 v = *(const float4*)(qrow + d4 * 4);
            Qs[(d0 + d4 * 4 + 0) * QS_W + r] = v.x;
            Qs[(d0 + d4 * 4 + 1) * QS_W + r] = v.y;
            Qs[(d0 + d4 * 4 + 2) * QS_W + r] = v.z;
            Qs[(d0 + d4 * 4 + 3) * QS_W + r] = v.w;
        }
    }

    float o[8][4];
    float m[8], l[8];
#pragma unroll
    for (int i = 0; i < 8; i++) {
        m[i] = -1e30f; l[i] = 0.0f;
#pragma unroll
        for (int j = 0; j < 4; j++) o[i][j] = 0.0f;
    }

    const float scale = 0.125f;            // 1/sqrt(64)
    const int ntiles = (qt + 1) * (BQ / BKEY);
    const int qrow0  = qt * BQ + r0;       // first row owned by this thread

    for (int kt = 0; kt < ntiles; kt++) {
        const int kb = kt * BKEY;

        // ---- Load K (transposed) and V (natural) tiles ----
        {
            const int rr = tid >> 2;           // key 0..63
            const int d0 = (tid & 3) * 16;     // 0,16,32,48
            const float* krow = base + (size_t)(kb + rr) * QKVD + DIM + d0;
            const float* vrow = krow + DIM;
#pragma unroll
            for (int d4 = 0; d4 < 4; d4++) {
                float4 kv4 = *(const float4*)(krow + d4 * 4);
                Ks[(d0 + d4 * 4 + 0) * KS_W + rr] = kv4.x;
                Ks[(d0 + d4 * 4 + 1) * KS_W + rr] = kv4.y;
                Ks[(d0 + d4 * 4 + 2) * KS_W + rr] = kv4.z;
                Ks[(d0 + d4 * 4 + 3) * KS_W + rr] = kv4.w;
                *(float4*)&Vs[rr * 64 + d0 + d4 * 4] = *(const float4*)(vrow + d4 * 4);
            }
        }
        __syncthreads();

        // ---- S = Q @ K^T (mini-GEMM, 8x4 microtile) ----
        float s[8][4];
#pragma unroll
        for (int i = 0; i < 8; i++)
#pragma unroll
            for (int j = 0; j < 4; j++) s[i][j] = 0.0f;

#pragma unroll 8
        for (int kk = 0; kk < 64; kk++) {
            float qv[8], kv[4];
#pragma unroll
            for (int i = 0; i < 8; i++) qv[i] = Qs[kk * QS_W + r0 + i];
#pragma unroll
            for (int j = 0; j < 4; j++) kv[j] = Ks[kk * KS_W + c0 + j];
#pragma unroll
            for (int i = 0; i < 8; i++)
#pragma unroll
                for (int j = 0; j < 4; j++)
                    s[i][j] = fmaf(qv[i], kv[j], s[i][j]);
        }

        // ---- Online softmax over this 64-key tile ----
        // Block-uniform predicate: tile fully unmasked for every row in block?
        const bool full_tile = (kb + BKEY - 1) <= qt * BQ;

#pragma unroll
        for (int i = 0; i < 8; i++) {
            const int row = qrow0 + i;
            if (full_tile) {
#pragma unroll
                for (int j = 0; j < 4; j++) s[i][j] *= scale;
            } else {
#pragma unroll
                for (int j = 0; j < 4; j++) {
                    const int c = kb + c0 + j;
                    s[i][j] = (c <= row) ? s[i][j] * scale : -1e30f;
                }
            }
            float tm = fmaxf(fmaxf(s[i][0], s[i][1]), fmaxf(s[i][2], s[i][3]));
            tm = fmaxf(tm, __shfl_xor_sync(0xffffffffu, tm, 1));
            tm = fmaxf(tm, __shfl_xor_sync(0xffffffffu, tm, 2));
            tm = fmaxf(tm, __shfl_xor_sync(0xffffffffu, tm, 4));
            tm = fmaxf(tm, __shfl_xor_sync(0xffffffffu, tm, 8));

            const float nm   = fmaxf(m[i], tm);
            const float corr = __expf(m[i] - nm);
            float psum = 0.0f;
#pragma unroll
            for (int j = 0; j < 4; j++) {
                const float p = __expf(s[i][j] - nm);
                s[i][j] = p;
                psum += p;
            }
            psum += __shfl_xor_sync(0xffffffffu, psum, 1);
            psum += __shfl_xor_sync(0xffffffffu, psum, 2);
            psum += __shfl_xor_sync(0xffffffffu, psum, 4);
            psum += __shfl_xor_sync(0xffffffffu, psum, 8);

            l[i] = l[i] * corr + psum;
            m[i] = nm;
#pragma unroll
            for (int j = 0; j < 4; j++) o[i][j] *= corr;
        }

        // ---- Stage P to smem: Ps[k][r] ----
#pragma unroll
        for (int j = 0; j < 4; j++) {
#pragma unroll
            for (int i = 0; i < 8; i++)
                Ps[(c0 + j) * 128 + r0 + i] = s[i][j];
        }
        __syncthreads();

        // ---- O += P @ V (mini-GEMM) ----
#pragma unroll 8
        for (int k = 0; k < 64; k++) {
            float4 pa = *(const float4*)&Ps[k * 128 + r0];
            float4 pb = *(const float4*)&Ps[k * 128 + r0 + 4];
            float4 vv = *(const float4*)&Vs[k * 64 + c0];
            o[0][0] = fmaf(pa.x, vv.x, o[0][0]); o[0][1] = fmaf(pa.x, vv.y, o[0][1]);
            o[0][2] = fmaf(pa.x, vv.z, o[0][2]); o[0][3] = fmaf(pa.x, vv.w, o[0][3]);
            o[1][0] = fmaf(pa.y, vv.x, o[1][0]); o[1][1] = fmaf(pa.y, vv.y, o[1][1]);
            o[1][2] = fmaf(pa.y, vv.z, o[1][2]); o[1][3] = fmaf(pa.y, vv.w, o[1][3]);
            o[2][0] = fmaf(pa.z, vv.x, o[2][0]); o[2][1] = fmaf(pa.z, vv.y, o[2][1]);
            o[2][2] = fmaf(pa.z, vv.z, o[2][2]); o[2][3] = fmaf(pa.z, vv.w, o[2][3]);
            o[3][0] = fmaf(pa.w, vv.x, o[3][0]); o[3][1] = fmaf(pa.w, vv.y, o[3][1]);
            o[3][2] = fmaf(pa.w, vv.z, o[3][2]); o[3][3] = fmaf(pa.w, vv.w, o[3][3]);
            o[4][0] = fmaf(pb.x, vv.x, o[4][0]); o[4][1] = fmaf(pb.x, vv.y, o[4][1]);
            o[4][2] = fmaf(pb.x, vv.z, o[4][2]); o[4][3] = fmaf(pb.x, vv.w, o[4][3]);
            o[5][0] = fmaf(pb.y, vv.x, o[5][0]); o[5][1] = fmaf(pb.y, vv.y, o[5][1]);
            o[5][2] = fmaf(pb.y, vv.z, o[5][2]); o[5][3] = fmaf(pb.y, vv.w, o[5][3]);
            o[6][0] = fmaf(pb.z, vv.x, o[6][0]); o[6][1] = fmaf(pb.z, vv.y, o[6][1]);
            o[6][2] = fmaf(pb.z, vv.z, o[6][2]); o[6][3] = fmaf(pb.z, vv.w, o[6][3]);
            o[7][0] = fmaf(pb.w, vv.x, o[7][0]); o[7][1] = fmaf(pb.w, vv.y, o[7][1]);
            o[7][2] = fmaf(pb.w, vv.z, o[7][2]); o[7][3] = fmaf(pb.w, vv.w, o[7][3]);
        }
        __syncthreads();
    }

    // ---- Epilogue: normalize and store ----
#pragma unroll
    for (int i = 0; i < 8; i++) {
        const float inv = 1.0f / l[i];
        float* orow = aout + ((size_t)b * SEQ + qrow0 + i) * DIM + h * HD + c0;
        float4 v;
        v.x = o[i][0] * inv; v.y = o[i][1] * inv;
        v.z = o[i][2] * inv; v.w = o[i][3] * inv;
        *(float4*)orow = v;
    }
}

// ---------------------------------------------------------------------------
extern "C" void kernel_launch(void* const* d_in, const int* in_sizes, int n_in,
                              void* d_out, int out_size)
{
    const float* x     = (const float*)d_in[0];   // [B,N,D]
    const float* W_qkv = (const float*)d_in[1];   // [3D,D]
    const float* b_qkv = (const float*)d_in[2];   // [3D]
    const float* W_out = (const float*)d_in[3];   // [D,D]
    const float* b_out = (const float*)d_in[4];   // [D]
    float* out = (float*)d_out;                   // [B,N,D]

    float* qkv  = nullptr;
    float* aout = nullptr;
    cudaGetSymbolAddress((void**)&qkv,  g_qkv);
    cudaGetSymbolAddress((void**)&aout, g_aout);

    // Set once on the pre-capture correctness call; harmless no-op after.
    cudaFuncSetAttribute(attn_kernel,
                         cudaFuncAttributeMaxDynamicSharedMemorySize,
                         ATTN_SMEM_BYTES);

    const int M = BATCH * SEQ;  // 4096

    // 1) QKV projection
    {
        dim3 grid(QKVD / BN, M / BM);
        sgemm_nt_bias<<<grid, 256>>>(M, QKVD, DIM, x, W_qkv, b_qkv, qkv);
    }

    // 2) Causal flash attention
    {
        dim3 grid(SEQ / BQ, HEADS, BATCH);
        attn_kernel<<<grid, 256, ATTN_SMEM_BYTES>>>(qkv, aout);
    }

    // 3) Output projection
    {
        dim3 grid(DIM / BN, M / BM);
        sgemm_nt_bias<<<grid, 256>>>(M, DIM, DIM, aout, W_out, b_out, out);
    }
}

// round 5
// speedup vs baseline: 2.9876x; 1.6013x over previous
#include <cuda_runtime.h>
#include <cuda_bf16.h>
#include <math.h>
#include <stdint.h>

// Problem constants
#define BATCH 2
#define SEQ   2048
#define DIM   1024
#define HEADS 16
#define HD    64
#define QKVD  3072   // 3*DIM

// Scratch (alloc-free rule: __device__ globals)
__device__ float g_qkv [(size_t)BATCH * SEQ * QKVD];   // [B, N, 3D]
__device__ float g_aout[(size_t)BATCH * SEQ * DIM];    // [B, N, D]

// ============================================================================
// Generic-PTX tensor-core helpers (compute_103-safe: sm_80-era mma/ldmatrix)
// ============================================================================
__device__ __forceinline__ uint32_t smem_u32(const void* p) {
    uint32_t a;
    asm("{ .reg .u64 t; cvta.to.shared.u64 t, %1; cvt.u32.u64 %0, t; }"
        : "=r"(a) : "l"(p));
    return a;
}

__device__ __forceinline__ void ldsm_x4(uint32_t& r0, uint32_t& r1,
                                        uint32_t& r2, uint32_t& r3,
                                        uint32_t addr) {
    asm volatile("ldmatrix.sync.aligned.m8n8.x4.shared.b16 {%0,%1,%2,%3}, [%4];"
                 : "=r"(r0), "=r"(r1), "=r"(r2), "=r"(r3) : "r"(addr));
}

__device__ __forceinline__ void mma_bf16(float* d, const uint32_t* a,
                                         const uint32_t* b) {
    asm volatile(
        "mma.sync.aligned.m16n8k16.row.col.f32.bf16.bf16.f32 "
        "{%0,%1,%2,%3}, {%4,%5,%6,%7}, {%8,%9}, {%0,%1,%2,%3};"
        : "+f"(d[0]), "+f"(d[1]), "+f"(d[2]), "+f"(d[3])
        : "r"(a[0]), "r"(a[1]), "r"(a[2]), "r"(a[3]), "r"(b[0]), "r"(b[1]));
}

// Split two fp32 into bf16 hi + bf16 lo (residual), packed as bf16x2 words.
__device__ __forceinline__ void split2(float x, float y,
                                       uint32_t& hi, uint32_t& lo) {
    __nv_bfloat162 h = __floats2bfloat162_rn(x, y);
    float rx = x - __bfloat162float(__low2bfloat16(h));
    float ry = y - __bfloat162float(__high2bfloat16(h));
    __nv_bfloat162 l = __floats2bfloat162_rn(rx, ry);
    hi = *(uint32_t*)&h;
    lo = *(uint32_t*)&l;
}

// ============================================================================
// bf16x3 tensor-core GEMM:  C[M,N_] = A[M,K] @ B[N_,K]^T + bias[N_]
// CTA tile 128x128, K-chunk 64, 8 warps (4m x 2n), warp tile 32x64.
// smem pitch 72 bf16 (144 B) -> conflict-free ldmatrix without swizzle.
// ============================================================================
#define GKC   64
#define GPITCH 72                                  // bf16 elems per smem row
#define GTILE_B (128 * GPITCH * 2)                 // 18432 B per tile
#define GSTAGE_B (4 * GTILE_B)                     // Ah,Al,Bh,Bl
#define G_SMEM_BYTES (2 * GSTAGE_B)                // 147456 B

__global__ __launch_bounds__(256, 1) void gemm_tc(
    int M, int N_, int K,
    const float* __restrict__ A,
    const float* __restrict__ B,
    const float* __restrict__ bias,
    float* __restrict__ C)
{
    extern __shared__ __align__(16) char sm[];

    const int tid = threadIdx.x;
    const int wid = tid >> 5;
    const int lane = tid & 31;

    const int n0 = blockIdx.x * 128;
    const int m0 = blockIdx.y * 128;

    const int warp_m = wid & 3;         // 0..3 -> m offset 32*warp_m
    const int warp_n = wid >> 2;        // 0..1 -> n offset 64*warp_n

    // Loader mapping: 16 rows per pass, 16 threads cover 64 cols (float4)
    const int lrow = tid >> 4;          // 0..15
    const int lcol = (tid & 15) * 4;    // 0..60

    float acc[2][8][4];
#pragma unroll
    for (int mt = 0; mt < 2; mt++)
#pragma unroll
        for (int nt = 0; nt < 8; nt++)
#pragma unroll
            for (int r = 0; r < 4; r++) acc[mt][nt][r] = 0.0f;

    // ldmatrix lane address components (in bf16-elem units, x2 for bytes)
    const int a_row = warp_m * 32 + (lane & 7) + ((lane >> 3) & 1) * 8;
    const int a_kof = ((lane >> 4) & 1) * 8;
    const int b_row = warp_n * 64 + (lane & 7) + ((lane >> 4) & 1) * 8;
    const int b_kof = ((lane >> 3) & 1) * 8;

    const int nchunk = K / GKC;

    // ---- Loader: fill stage s with chunk ic ----
    auto load_chunk = [&](int ic, int s) {
        char* base = sm + (size_t)s * GSTAGE_B;
        char* Ah = base;
        char* Al = base + GTILE_B;
        char* Bh = base + 2 * GTILE_B;
        char* Bl = base + 3 * GTILE_B;
        const int kc = ic * GKC;
#pragma unroll
        for (int it = 0; it < 8; it++) {
            const int row = lrow + it * 16;
            const uint32_t soff = (uint32_t)(row * GPITCH + lcol) * 2;
            {
                float4 v = *(const float4*)(A + (size_t)(m0 + row) * K + kc + lcol);
                uint2 hu, lu;
                split2(v.x, v.y, hu.x, lu.x);
                split2(v.z, v.w, hu.y, lu.y);
                *(uint2*)(Ah + soff) = hu;
                *(uint2*)(Al + soff) = lu;
            }
            {
                float4 v = *(const float4*)(B + (size_t)(n0 + row) * K + kc + lcol);
                uint2 hu, lu;
                split2(v.x, v.y, hu.x, lu.x);
                split2(v.z, v.w, hu.y, lu.y);
                *(uint2*)(Bh + soff) = hu;
                *(uint2*)(Bl + soff) = lu;
            }
        }
    };

    load_chunk(0, 0);
    __syncthreads();

    for (int ic = 0; ic < nchunk; ic++) {
        const int p = ic & 1;
        if (ic + 1 < nchunk) load_chunk(ic + 1, p ^ 1);

        // ---- MMA on stage p ----
        {
            char* base = sm + (size_t)p * GSTAGE_B;
            const uint32_t sAh = smem_u32(base);
            const uint32_t sAl = sAh + GTILE_B;
            const uint32_t sBh = sAh + 2 * GTILE_B;
            const uint32_t sBl = sAh + 3 * GTILE_B;

#pragma unroll
            for (int ks = 0; ks < 4; ks++) {
                const int k16 = ks * 16;
                uint32_t ah[2][4], al[2][4];
#pragma unroll
                for (int mt = 0; mt < 2; mt++) {
                    const uint32_t aoff =
                        (uint32_t)((a_row + mt * 16) * GPITCH + k16 + a_kof) * 2;
                    ldsm_x4(ah[mt][0], ah[mt][1], ah[mt][2], ah[mt][3], sAh + aoff);
                    ldsm_x4(al[mt][0], al[mt][1], al[mt][2], al[mt][3], sAl + aoff);
                }
                uint32_t bh[8][2], bl[8][2];
#pragma unroll
                for (int ntp = 0; ntp < 4; ntp++) {
                    const uint32_t boff =
                        (uint32_t)((b_row + ntp * 16) * GPITCH + k16 + b_kof) * 2;
                    ldsm_x4(bh[2 * ntp][0], bh[2 * ntp][1],
                            bh[2 * ntp + 1][0], bh[2 * ntp + 1][1], sBh + boff);
                    ldsm_x4(bl[2 * ntp][0], bl[2 * ntp][1],
                            bl[2 * ntp + 1][0], bl[2 * ntp + 1][1], sBl + boff);
                }
#pragma unroll
                for (int mt = 0; mt < 2; mt++)
#pragma unroll
                    for (int nt = 0; nt < 8; nt++) {
                        mma_bf16(acc[mt][nt], ah[mt], bh[nt]);
                        mma_bf16(acc[mt][nt], ah[mt], bl[nt]);
                        mma_bf16(acc[mt][nt], al[mt], bh[nt]);
                    }
            }
        }
        __syncthreads();
    }

    // ---- Epilogue: bias + store (D frag: rows t/4 & t/4+8, cols (t%4)*2) ----
    const int er0 = m0 + warp_m * 32 + (lane >> 2);
    const int ec0 = n0 + warp_n * 64 + (lane & 3) * 2;
#pragma unroll
    for (int mt = 0; mt < 2; mt++) {
#pragma unroll
        for (int nt = 0; nt < 8; nt++) {
            const int col = ec0 + nt * 8;
            const float bx = bias[col], by = bias[col + 1];
            float* c0 = C + (size_t)(er0 + mt * 16) * N_ + col;
            float* c1 = C + (size_t)(er0 + mt * 16 + 8) * N_ + col;
            float2 v0 = make_float2(acc[mt][nt][0] + bx, acc[mt][nt][1] + by);
            float2 v1 = make_float2(acc[mt][nt][2] + bx, acc[mt][nt][3] + by);
            *(float2*)c0 = v0;
            *(float2*)c1 = v1;
        }
    }
}

// ---------------------------------------------------------------------------
// Flash attention v2-style (causal) — unchanged from R3.
// ---------------------------------------------------------------------------
#define BQ  128
#define BKEY 64
#define QS_W 129
#define KS_W 65
#define ATTN_SMEM_BYTES ((64*129 + 64*65 + 64*64 + 64*128) * 4)

__global__ __launch_bounds__(256) void attn_kernel(
    const float* __restrict__ qkv,  // [B, N, 3D]
    float* __restrict__ aout)       // [B, N, D]
{
    extern __shared__ float smf[];
    float* Qs = smf;                       // [64][129]
    float* Ks = Qs + 64 * QS_W;            // [64][65]
    float* Vs = Ks + 64 * KS_W;            // [64][64]
    float* Ps = Vs + 64 * 64;              // [64][128]

    const int qt = gridDim.x - 1 - blockIdx.x;
    const int h  = blockIdx.y;
    const int b  = blockIdx.z;
    const int tid = threadIdx.x;
    const int tx = tid & 15;
    const int ty = tid >> 4;
    const int r0 = ty * 8;
    const int c0 = tx * 4;

    const float* base = qkv + (size_t)b * SEQ * QKVD + h * HD;

    {
        const int r  = tid >> 1;
        const int d0 = (tid & 1) * 32;
        const float* qrow = base + (size_t)(qt * BQ + r) * QKVD + d0;
#pragma unroll
        for (int d4 = 0; d4 < 8; d4++) {
            float4 v = *(const float4*)(qrow + d4 * 4);
            Qs[(d0 + d4 * 4 + 0) * QS_W + r] = v.x;
            Qs[(d0 + d4 * 4 + 1) * QS_W + r] = v.y;
            Qs[(d0 + d4 * 4 + 2) * QS_W + r] = v.z;
            Qs[(d0 + d4 * 4 + 3) * QS_W + r] = v.w;
        }
    }

    float o[8][4];
    float m[8], l[8];
#pragma unroll
    for (int i = 0; i < 8; i++) {
        m[i] = -1e30f; l[i] = 0.0f;
#pragma unroll
        for (int j = 0; j < 4; j++) o[i][j] = 0.0f;
    }

    const float scale = 0.125f;
    const int ntiles = (qt + 1) * (BQ / BKEY);
    const int qrow0  = qt * BQ + r0;

    for (int kt = 0; kt < ntiles; kt++) {
        const int kb = kt * BKEY;
        {
            const int rr = tid >> 2;
            const int d0 = (tid & 3) * 16;
            const float* krow = base + (size_t)(kb + rr) * QKVD + DIM + d0;
            const float* vrow = krow + DIM;
#pragma unroll
            for (int d4 = 0; d4 < 4; d4++) {
                float4 kv4 = *(const float4*)(krow + d4 * 4);
                Ks[(d0 + d4 * 4 + 0) * KS_W + rr] = kv4.x;
                Ks[(d0 + d4 * 4 + 1) * KS_W + rr] = kv4.y;
                Ks[(d0 + d4 * 4 + 2) * KS_W + rr] = kv4.z;
                Ks[(d0 + d4 * 4 + 3) * KS_W + rr] = kv4.w;
                *(float4*)&Vs[rr * 64 + d0 + d4 * 4] = *(const float4*)(vrow + d4 * 4);
            }
        }
        __syncthreads();

        float s[8][4];
#pragma unroll
        for (int i = 0; i < 8; i++)
#pragma unroll
            for (int j = 0; j < 4; j++) s[i][j] = 0.0f;

#pragma unroll 8
        for (int kk = 0; kk < 64; kk++) {
            float qv[8], kv[4];
#pragma unroll
            for (int i = 0; i < 8; i++) qv[i] = Qs[kk * QS_W + r0 + i];
#pragma unroll
            for (int j = 0; j < 4; j++) kv[j] = Ks[kk * KS_W + c0 + j];
#pragma unroll
            for (int i = 0; i < 8; i++)
#pragma unroll
                for (int j = 0; j < 4; j++)
                    s[i][j] = fmaf(qv[i], kv[j], s[i][j]);
        }

        const bool full_tile = (kb + BKEY - 1) <= qt * BQ;

#pragma unroll
        for (int i = 0; i < 8; i++) {
            const int row = qrow0 + i;
            if (full_tile) {
#pragma unroll
                for (int j = 0; j < 4; j++) s[i][j] *= scale;
            } else {
#pragma unroll
                for (int j = 0; j < 4; j++) {
                    const int c = kb + c0 + j;
                    s[i][j] = (c <= row) ? s[i][j] * scale : -1e30f;
                }
            }
            float tm = fmaxf(fmaxf(s[i][0], s[i][1]), fmaxf(s[i][2], s[i][3]));
            tm = fmaxf(tm, __shfl_xor_sync(0xffffffffu, tm, 1));
            tm = fmaxf(tm, __shfl_xor_sync(0xffffffffu, tm, 2));
            tm = fmaxf(tm, __shfl_xor_sync(0xffffffffu, tm, 4));
            tm = fmaxf(tm, __shfl_xor_sync(0xffffffffu, tm, 8));

            const float nm   = fmaxf(m[i], tm);
            const float corr = __expf(m[i] - nm);
            float psum = 0.0f;
#pragma unroll
            for (int j = 0; j < 4; j++) {
                const float p = __expf(s[i][j] - nm);
                s[i][j] = p;
                psum += p;
            }
            psum += __shfl_xor_sync(0xffffffffu, psum, 1);
            psum += __shfl_xor_sync(0xffffffffu, psum, 2);
            psum += __shfl_xor_sync(0xffffffffu, psum, 4);
            psum += __shfl_xor_sync(0xffffffffu, psum, 8);

            l[i] = l[i] * corr + psum;
            m[i] = nm;
#pragma unroll
            for (int j = 0; j < 4; j++) o[i][j] *= corr;
        }

#pragma unroll
        for (int j = 0; j < 4; j++) {
#pragma unroll
            for (int i = 0; i < 8; i++)
                Ps[(c0 + j) * 128 + r0 + i] = s[i][j];
        }
        __syncthreads();

#pragma unroll 8
        for (int k = 0; k < 64; k++) {
            float4 pa = *(const float4*)&Ps[k * 128 + r0];
            float4 pb = *(const float4*)&Ps[k * 128 + r0 + 4];
            float4 vv = *(const float4*)&Vs[k * 64 + c0];
            o[0][0] = fmaf(pa.x, vv.x, o[0][0]); o[0][1] = fmaf(pa.x, vv.y, o[0][1]);
            o[0][2] = fmaf(pa.x, vv.z, o[0][2]); o[0][3] = fmaf(pa.x, vv.w, o[0][3]);
            o[1][0] = fmaf(pa.y, vv.x, o[1][0]); o[1][1] = fmaf(pa.y, vv.y, o[1][1]);
            o[1][2] = fmaf(pa.y, vv.z, o[1][2]); o[1][3] = fmaf(pa.y, vv.w, o[1][3]);
            o[2][0] = fmaf(pa.z, vv.x, o[2][0]); o[2][1] = fmaf(pa.z, vv.y, o[2][1]);
            o[2][2] = fmaf(pa.z, vv.z, o[2][2]); o[2][3] = fmaf(pa.z, vv.w, o[2][3]);
            o[3][0] = fmaf(pa.w, vv.x, o[3][0]); o[3][1] = fmaf(pa.w, vv.y, o[3][1]);
            o[3][2] = fmaf(pa.w, vv.z, o[3][2]); o[3][3] = fmaf(pa.w, vv.w, o[3][3]);
            o[4][0] = fmaf(pb.x, vv.x, o[4][0]); o[4][1] = fmaf(pb.x, vv.y, o[4][1]);
            o[4][2] = fmaf(pb.x, vv.z, o[4][2]); o[4][3] = fmaf(pb.x, vv.w, o[4][3]);
            o[5][0] = fmaf(pb.y, vv.x, o[5][0]); o[5][1] = fmaf(pb.y, vv.y, o[5][1]);
            o[5][2] = fmaf(pb.y, vv.z, o[5][2]); o[5][3] = fmaf(pb.y, vv.w, o[5][3]);
            o[6][0] = fmaf(pb.z, vv.x, o[6][0]); o[6][1] = fmaf(pb.z, vv.y, o[6][1]);
            o[6][2] = fmaf(pb.z, vv.z, o[6][2]); o[6][3] = fmaf(pb.z, vv.w, o[6][3]);
            o[7][0] = fmaf(pb.w, vv.x, o[7][0]); o[7][1] = fmaf(pb.w, vv.y, o[7][1]);
            o[7][2] = fmaf(pb.w, vv.z, o[7][2]); o[7][3] = fmaf(pb.w, vv.w, o[7][3]);
        }
        __syncthreads();
    }

#pragma unroll
    for (int i = 0; i < 8; i++) {
        const float inv = 1.0f / l[i];
        float* orow = aout + ((size_t)b * SEQ + qrow0 + i) * DIM + h * HD + c0;
        float4 v;
        v.x = o[i][0] * inv; v.y = o[i][1] * inv;
        v.z = o[i][2] * inv; v.w = o[i][3] * inv;
        *(float4*)orow = v;
    }
}

// ---------------------------------------------------------------------------
extern "C" void kernel_launch(void* const* d_in, const int* in_sizes, int n_in,
                              void* d_out, int out_size)
{
    const float* x     = (const float*)d_in[0];   // [B,N,D]
    const float* W_qkv = (const float*)d_in[1];   // [3D,D]
    const float* b_qkv = (const float*)d_in[2];   // [3D]
    const float* W_out = (const float*)d_in[3];   // [D,D]
    const float* b_out = (const float*)d_in[4];   // [D]
    float* out = (float*)d_out;                   // [B,N,D]

    float* qkv  = nullptr;
    float* aout = nullptr;
    cudaGetSymbolAddress((void**)&qkv,  g_qkv);
    cudaGetSymbolAddress((void**)&aout, g_aout);

    cudaFuncSetAttribute(gemm_tc,
                         cudaFuncAttributeMaxDynamicSharedMemorySize,
                         G_SMEM_BYTES);
    cudaFuncSetAttribute(attn_kernel,
                         cudaFuncAttributeMaxDynamicSharedMemorySize,
                         ATTN_SMEM_BYTES);

    const int M = BATCH * SEQ;  // 4096

    // 1) QKV projection (mma.sync bf16x3)
    {
        dim3 grid(QKVD / 128, M / 128);
        gemm_tc<<<grid, 256, G_SMEM_BYTES>>>(M, QKVD, DIM, x, W_qkv, b_qkv, qkv);
    }

    // 2) Causal flash attention
    {
        dim3 grid(SEQ / BQ, HEADS, BATCH);
        attn_kernel<<<grid, 256, ATTN_SMEM_BYTES>>>(qkv, aout);
    }

    // 3) Output projection (mma.sync bf16x3)
    {
        dim3 grid(DIM / 128, M / 128);
        gemm_tc<<<grid, 256, G_SMEM_BYTES>>>(M, DIM, DIM, aout, W_out, b_out, out);
    }
}

// round 6
// speedup vs baseline: 5.0629x; 1.6946x over previous
#include <cuda_runtime.h>
#include <cuda_bf16.h>
#include <math.h>
#include <stdint.h>

// Problem constants
#define BATCH 2
#define SEQ   2048
#define DIM   1024
#define HEADS 16
#define HD    64
#define QKVD  3072   // 3*DIM

// Scratch (alloc-free rule: __device__ globals)
__device__ float g_qkv [(size_t)BATCH * SEQ * QKVD];   // [B, N, 3D]
__device__ float g_aout[(size_t)BATCH * SEQ * DIM];    // [B, N, D]

// ============================================================================
// Generic-PTX tensor-core helpers (compute_103-safe: sm_80-era mma/ldmatrix)
// ============================================================================
__device__ __forceinline__ uint32_t smem_u32(const void* p) {
    uint32_t a;
    asm("{ .reg .u64 t; cvta.to.shared.u64 t, %1; cvt.u32.u64 %0, t; }"
        : "=r"(a) : "l"(p));
    return a;
}

__device__ __forceinline__ void ldsm_x4(uint32_t& r0, uint32_t& r1,
                                        uint32_t& r2, uint32_t& r3,
                                        uint32_t addr) {
    asm volatile("ldmatrix.sync.aligned.m8n8.x4.shared.b16 {%0,%1,%2,%3}, [%4];"
                 : "=r"(r0), "=r"(r1), "=r"(r2), "=r"(r3) : "r"(addr));
}

__device__ __forceinline__ void mma_bf16(float* d, const uint32_t* a,
                                         const uint32_t* b) {
    asm volatile(
        "mma.sync.aligned.m16n8k16.row.col.f32.bf16.bf16.f32 "
        "{%0,%1,%2,%3}, {%4,%5,%6,%7}, {%8,%9}, {%0,%1,%2,%3};"
        : "+f"(d[0]), "+f"(d[1]), "+f"(d[2]), "+f"(d[3])
        : "r"(a[0]), "r"(a[1]), "r"(a[2]), "r"(a[3]), "r"(b[0]), "r"(b[1]));
}

// Split two fp32 into bf16 hi + bf16 lo (residual), packed as bf16x2 words.
__device__ __forceinline__ void split2(float x, float y,
                                       uint32_t& hi, uint32_t& lo) {
    __nv_bfloat162 h = __floats2bfloat162_rn(x, y);
    float rx = x - __bfloat162float(__low2bfloat16(h));
    float ry = y - __bfloat162float(__high2bfloat16(h));
    __nv_bfloat162 l = __floats2bfloat162_rn(rx, ry);
    hi = *(uint32_t*)&h;
    lo = *(uint32_t*)&l;
}

// ============================================================================
// bf16x3 tensor-core GEMM:  C[M,N_] = A[M,K] @ B[N_,K]^T + bias[N_]
// (unchanged from R5)
// ============================================================================
#define GKC   64
#define GPITCH 72
#define GTILE_B (128 * GPITCH * 2)
#define GSTAGE_B (4 * GTILE_B)
#define G_SMEM_BYTES (2 * GSTAGE_B)

__global__ __launch_bounds__(256, 1) void gemm_tc(
    int M, int N_, int K,
    const float* __restrict__ A,
    const float* __restrict__ B,
    const float* __restrict__ bias,
    float* __restrict__ C)
{
    extern __shared__ __align__(16) char sm[];

    const int tid = threadIdx.x;
    const int wid = tid >> 5;
    const int lane = tid & 31;

    const int n0 = blockIdx.x * 128;
    const int m0 = blockIdx.y * 128;

    const int warp_m = wid & 3;
    const int warp_n = wid >> 2;

    const int lrow = tid >> 4;
    const int lcol = (tid & 15) * 4;

    float acc[2][8][4];
#pragma unroll
    for (int mt = 0; mt < 2; mt++)
#pragma unroll
        for (int nt = 0; nt < 8; nt++)
#pragma unroll
            for (int r = 0; r < 4; r++) acc[mt][nt][r] = 0.0f;

    const int a_row = warp_m * 32 + (lane & 7) + ((lane >> 3) & 1) * 8;
    const int a_kof = ((lane >> 4) & 1) * 8;
    const int b_row = warp_n * 64 + (lane & 7) + ((lane >> 4) & 1) * 8;
    const int b_kof = ((lane >> 3) & 1) * 8;

    const int nchunk = K / GKC;

    auto load_chunk = [&](int ic, int s) {
        char* base = sm + (size_t)s * GSTAGE_B;
        char* Ah = base;
        char* Al = base + GTILE_B;
        char* Bh = base + 2 * GTILE_B;
        char* Bl = base + 3 * GTILE_B;
        const int kc = ic * GKC;
#pragma unroll
        for (int it = 0; it < 8; it++) {
            const int row = lrow + it * 16;
            const uint32_t soff = (uint32_t)(row * GPITCH + lcol) * 2;
            {
                float4 v = *(const float4*)(A + (size_t)(m0 + row) * K + kc + lcol);
                uint2 hu, lu;
                split2(v.x, v.y, hu.x, lu.x);
                split2(v.z, v.w, hu.y, lu.y);
                *(uint2*)(Ah + soff) = hu;
                *(uint2*)(Al + soff) = lu;
            }
            {
                float4 v = *(const float4*)(B + (size_t)(n0 + row) * K + kc + lcol);
                uint2 hu, lu;
                split2(v.x, v.y, hu.x, lu.x);
                split2(v.z, v.w, hu.y, lu.y);
                *(uint2*)(Bh + soff) = hu;
                *(uint2*)(Bl + soff) = lu;
            }
        }
    };

    load_chunk(0, 0);
    __syncthreads();

    for (int ic = 0; ic < nchunk; ic++) {
        const int p = ic & 1;
        if (ic + 1 < nchunk) load_chunk(ic + 1, p ^ 1);

        {
            char* base = sm + (size_t)p * GSTAGE_B;
            const uint32_t sAh = smem_u32(base);
            const uint32_t sAl = sAh + GTILE_B;
            const uint32_t sBh = sAh + 2 * GTILE_B;
            const uint32_t sBl = sAh + 3 * GTILE_B;

#pragma unroll
            for (int ks = 0; ks < 4; ks++) {
                const int k16 = ks * 16;
                uint32_t ah[2][4], al[2][4];
#pragma unroll
                for (int mt = 0; mt < 2; mt++) {
                    const uint32_t aoff =
                        (uint32_t)((a_row + mt * 16) * GPITCH + k16 + a_kof) * 2;
                    ldsm_x4(ah[mt][0], ah[mt][1], ah[mt][2], ah[mt][3], sAh + aoff);
                    ldsm_x4(al[mt][0], al[mt][1], al[mt][2], al[mt][3], sAl + aoff);
                }
                uint32_t bh[8][2], bl[8][2];
#pragma unroll
                for (int ntp = 0; ntp < 4; ntp++) {
                    const uint32_t boff =
                        (uint32_t)((b_row + ntp * 16) * GPITCH + k16 + b_kof) * 2;
                    ldsm_x4(bh[2 * ntp][0], bh[2 * ntp][1],
                            bh[2 * ntp + 1][0], bh[2 * ntp + 1][1], sBh + boff);
                    ldsm_x4(bl[2 * ntp][0], bl[2 * ntp][1],
                            bl[2 * ntp + 1][0], bl[2 * ntp + 1][1], sBl + boff);
                }
#pragma unroll
                for (int mt = 0; mt < 2; mt++)
#pragma unroll
                    for (int nt = 0; nt < 8; nt++) {
                        mma_bf16(acc[mt][nt], ah[mt], bh[nt]);
                        mma_bf16(acc[mt][nt], ah[mt], bl[nt]);
                        mma_bf16(acc[mt][nt], al[mt], bh[nt]);
                    }
            }
        }
        __syncthreads();
    }

    const int er0 = m0 + warp_m * 32 + (lane >> 2);
    const int ec0 = n0 + warp_n * 64 + (lane & 3) * 2;
#pragma unroll
    for (int mt = 0; mt < 2; mt++) {
#pragma unroll
        for (int nt = 0; nt < 8; nt++) {
            const int col = ec0 + nt * 8;
            const float bx = bias[col], by = bias[col + 1];
            float* c0 = C + (size_t)(er0 + mt * 16) * N_ + col;
            float* c1 = C + (size_t)(er0 + mt * 16 + 8) * N_ + col;
            *(float2*)c0 = make_float2(acc[mt][nt][0] + bx, acc[mt][nt][1] + by);
            *(float2*)c1 = make_float2(acc[mt][nt][2] + bx, acc[mt][nt][3] + by);
        }
    }
}

// ============================================================================
// Flash attention on tensor cores (bf16x3 split, FA2-style).
// Block: 128 q-rows x 1 head, 8 warps; warp owns 16 rows (m-split only).
// K-tiles of 64 keys. smem (bf16, pitch 72):
//   Qh[128][72] Ql[128][72] Kh[64][72] Kl[64][72] Vth[64][72] Vtl[64][72]
// Vt is V transposed: [dim][key].
// ============================================================================
#define APITCH 72
#define A_QTILE  (128 * APITCH * 2)     // 18432 B
#define A_KTILE  (64 * APITCH * 2)      //  9216 B
#define A_SMEM_BYTES (2 * A_QTILE + 4 * A_KTILE)   // 73728 B

__global__ __launch_bounds__(256, 1) void attn_tc(
    const float* __restrict__ qkv,  // [B, N, 3D]
    float* __restrict__ aout)       // [B, N, D]
{
    extern __shared__ __align__(16) char smema[];
    const uint32_t sQh  = smem_u32(smema);
    const uint32_t sQl  = sQh + A_QTILE;
    const uint32_t sKh  = sQl + A_QTILE;
    const uint32_t sKl  = sKh + A_KTILE;
    const uint32_t sVth = sKl + A_KTILE;
    const uint32_t sVtl = sVth + A_KTILE;

    const int qt = gridDim.x - 1 - blockIdx.x;   // heavy tiles first
    const int h  = blockIdx.y;
    const int b  = blockIdx.z;
    const int tid = threadIdx.x;
    const int wid = tid >> 5;
    const int lane = tid & 31;

    const float* base = qkv + (size_t)b * SEQ * QKVD + h * HD;

    const int lrow = tid >> 4;          // 0..15
    const int lcol = (tid & 15) * 4;    // 0..60 (dims)

    // ---- Load + split Q tile (128 x 64) ----
#pragma unroll
    for (int it = 0; it < 8; it++) {
        const int row = lrow + it * 16;
        float4 v = *(const float4*)(base + (size_t)(qt * 128 + row) * QKVD + lcol);
        uint2 hu, lu;
        split2(v.x, v.y, hu.x, lu.x);
        split2(v.z, v.w, hu.y, lu.y);
        const uint32_t soff = (uint32_t)(row * APITCH + lcol) * 2;
        *(uint2*)(smema + (sQh - smem_u32(smema)) + soff) = hu;   // Qh
        *(uint2*)(smema + (sQl - smem_u32(smema)) + soff) = lu;   // Ql
    }
    __syncthreads();

    // ---- Hoist Q fragments (loop-invariant) ----
    const int a_row = wid * 16 + (lane & 7) + ((lane >> 3) & 1) * 8;
    const int a_kof = ((lane >> 4) & 1) * 8;
    uint32_t qh[4][4], ql[4][4];
#pragma unroll
    for (int ks = 0; ks < 4; ks++) {
        const uint32_t off = (uint32_t)(a_row * APITCH + ks * 16 + a_kof) * 2;
        ldsm_x4(qh[ks][0], qh[ks][1], qh[ks][2], qh[ks][3], sQh + off);
        ldsm_x4(ql[ks][0], ql[ks][1], ql[ks][2], ql[ks][3], sQl + off);
    }

    const int b_row = (lane & 7) + ((lane >> 4) & 1) * 8;
    const int b_kof = ((lane >> 3) & 1) * 8;

    float o[8][4];
#pragma unroll
    for (int nt = 0; nt < 8; nt++)
#pragma unroll
        for (int r = 0; r < 4; r++) o[nt][r] = 0.0f;
    float m0 = -1e30f, m1 = -1e30f, l0 = 0.0f, l1 = 0.0f;

    const float scale = 0.125f;
    const int row_lo = qt * 128 + wid * 16 + (lane >> 2);
    const int row_hi = row_lo + 8;
    const int ntiles = (qt + 1) * 2;

    for (int kt = 0; kt < ntiles; kt++) {
        const int kb = kt * 64;

        // ---- Load + split K (natural) and V (transposed) tiles ----
#pragma unroll
        for (int it = 0; it < 4; it++) {
            const int row = lrow + it * 16;   // key index
            const float* kr = base + (size_t)(kb + row) * QKVD + DIM + lcol;
            {
                float4 v = *(const float4*)kr;
                uint2 hu, lu;
                split2(v.x, v.y, hu.x, lu.x);
                split2(v.z, v.w, hu.y, lu.y);
                const uint32_t soff = (uint32_t)(row * APITCH + lcol) * 2;
                *(uint2*)(smema + (sKh - sQh) + soff) = hu;
                *(uint2*)(smema + (sKl - sQh) + soff) = lu;
            }
            {
                float4 v = *(const float4*)(kr + DIM);
                float vals[4] = {v.x, v.y, v.z, v.w};
#pragma unroll
                for (int e = 0; e < 4; e++) {
                    __nv_bfloat16 hb = __float2bfloat16_rn(vals[e]);
                    float r = vals[e] - __bfloat162float(hb);
                    __nv_bfloat16 lb = __float2bfloat16_rn(r);
                    const uint32_t toff = (uint32_t)((lcol + e) * APITCH + row) * 2;
                    *(__nv_bfloat16*)(smema + (sVth - sQh) + toff) = hb;
                    *(__nv_bfloat16*)(smema + (sVtl - sQh) + toff) = lb;
                }
            }
        }
        __syncthreads();

        // ---- S = Q @ K^T ----
        float s[8][4];
#pragma unroll
        for (int nt = 0; nt < 8; nt++)
#pragma unroll
            for (int r = 0; r < 4; r++) s[nt][r] = 0.0f;

#pragma unroll
        for (int ks = 0; ks < 4; ks++) {
            uint32_t kh[8][2], kl[8][2];
#pragma unroll
            for (int ntp = 0; ntp < 4; ntp++) {
                const uint32_t off =
                    (uint32_t)((ntp * 16 + b_row) * APITCH + ks * 16 + b_kof) * 2;
                ldsm_x4(kh[2 * ntp][0], kh[2 * ntp][1],
                        kh[2 * ntp + 1][0], kh[2 * ntp + 1][1], sKh + off);
                ldsm_x4(kl[2 * ntp][0], kl[2 * ntp][1],
                        kl[2 * ntp + 1][0], kl[2 * ntp + 1][1], sKl + off);
            }
#pragma unroll
            for (int nt = 0; nt < 8; nt++) {
                mma_bf16(s[nt], qh[ks], kh[nt]);
                mma_bf16(s[nt], qh[ks], kl[nt]);
                mma_bf16(s[nt], ql[ks], kh[nt]);
            }
        }

        // ---- Scale + causal mask ----
        const bool full = (kb + 63) <= qt * 128;
        if (full) {
#pragma unroll
            for (int nt = 0; nt < 8; nt++)
#pragma unroll
                for (int r = 0; r < 4; r++) s[nt][r] *= scale;
        } else {
#pragma unroll
            for (int nt = 0; nt < 8; nt++) {
                const int col = kb + nt * 8 + (lane & 3) * 2;
                s[nt][0] = (col     <= row_lo) ? s[nt][0] * scale : -1e30f;
                s[nt][1] = (col + 1 <= row_lo) ? s[nt][1] * scale : -1e30f;
                s[nt][2] = (col     <= row_hi) ? s[nt][2] * scale : -1e30f;
                s[nt][3] = (col + 1 <= row_hi) ? s[nt][3] * scale : -1e30f;
            }
        }

        // ---- Online softmax (rows lane>>2 and +8; quad shuffles) ----
        float tm0 = -1e30f, tm1 = -1e30f;
#pragma unroll
        for (int nt = 0; nt < 8; nt++) {
            tm0 = fmaxf(tm0, fmaxf(s[nt][0], s[nt][1]));
            tm1 = fmaxf(tm1, fmaxf(s[nt][2], s[nt][3]));
        }
        tm0 = fmaxf(tm0, __shfl_xor_sync(0xffffffffu, tm0, 1));
        tm0 = fmaxf(tm0, __shfl_xor_sync(0xffffffffu, tm0, 2));
        tm1 = fmaxf(tm1, __shfl_xor_sync(0xffffffffu, tm1, 1));
        tm1 = fmaxf(tm1, __shfl_xor_sync(0xffffffffu, tm1, 2));

        const float nm0 = fmaxf(m0, tm0);
        const float nm1 = fmaxf(m1, tm1);
        const float corr0 = __expf(m0 - nm0);
        const float corr1 = __expf(m1 - nm1);

        float ps0 = 0.0f, ps1 = 0.0f;
#pragma unroll
        for (int nt = 0; nt < 8; nt++) {
            s[nt][0] = __expf(s[nt][0] - nm0); ps0 += s[nt][0];
            s[nt][1] = __expf(s[nt][1] - nm0); ps0 += s[nt][1];
            s[nt][2] = __expf(s[nt][2] - nm1); ps1 += s[nt][2];
            s[nt][3] = __expf(s[nt][3] - nm1); ps1 += s[nt][3];
        }
        ps0 += __shfl_xor_sync(0xffffffffu, ps0, 1);
        ps0 += __shfl_xor_sync(0xffffffffu, ps0, 2);
        ps1 += __shfl_xor_sync(0xffffffffu, ps1, 1);
        ps1 += __shfl_xor_sync(0xffffffffu, ps1, 2);

        l0 = l0 * corr0 + ps0; m0 = nm0;
        l1 = l1 * corr1 + ps1; m1 = nm1;
#pragma unroll
        for (int nt = 0; nt < 8; nt++) {
            o[nt][0] *= corr0; o[nt][1] *= corr0;
            o[nt][2] *= corr1; o[nt][3] *= corr1;
        }

        // ---- O += P @ V (P repacked in registers, split Ph/Pl) ----
#pragma unroll
        for (int ks = 0; ks < 4; ks++) {
            uint32_t ah[4], al[4];
            const int j = 2 * ks;
            split2(s[j][0],     s[j][1],     ah[0], al[0]);
            split2(s[j][2],     s[j][3],     ah[1], al[1]);
            split2(s[j + 1][0], s[j + 1][1], ah[2], al[2]);
            split2(s[j + 1][2], s[j + 1][3], ah[3], al[3]);

            uint32_t vh[8][2], vl[8][2];
#pragma unroll
            for (int ntp = 0; ntp < 4; ntp++) {
                const uint32_t off =
                    (uint32_t)((ntp * 16 + b_row) * APITCH + ks * 16 + b_kof) * 2;
                ldsm_x4(vh[2 * ntp][0], vh[2 * ntp][1],
                        vh[2 * ntp + 1][0], vh[2 * ntp + 1][1], sVth + off);
                ldsm_x4(vl[2 * ntp][0], vl[2 * ntp][1],
                        vl[2 * ntp + 1][0], vl[2 * ntp + 1][1], sVtl + off);
            }
#pragma unroll
            for (int nt = 0; nt < 8; nt++) {
                mma_bf16(o[nt], ah, vh[nt]);
                mma_bf16(o[nt], ah, vl[nt]);
                mma_bf16(o[nt], al, vh[nt]);
            }
        }
        __syncthreads();
    }

    // ---- Epilogue: normalize + store ----
    const float inv0 = 1.0f / l0;
    const float inv1 = 1.0f / l1;
#pragma unroll
    for (int nt = 0; nt < 8; nt++) {
        const int col = nt * 8 + (lane & 3) * 2;
        float* p0 = aout + ((size_t)b * SEQ + row_lo) * DIM + h * HD + col;
        float* p1 = aout + ((size_t)b * SEQ + row_hi) * DIM + h * HD + col;
        *(float2*)p0 = make_float2(o[nt][0] * inv0, o[nt][1] * inv0);
        *(float2*)p1 = make_float2(o[nt][2] * inv1, o[nt][3] * inv1);
    }
}

// ---------------------------------------------------------------------------
extern "C" void kernel_launch(void* const* d_in, const int* in_sizes, int n_in,
                              void* d_out, int out_size)
{
    const float* x     = (const float*)d_in[0];
    const float* W_qkv = (const float*)d_in[1];
    const float* b_qkv = (const float*)d_in[2];
    const float* W_out = (const float*)d_in[3];
    const float* b_out = (const float*)d_in[4];
    float* out = (float*)d_out;

    float* qkv  = nullptr;
    float* aout = nullptr;
    cudaGetSymbolAddress((void**)&qkv,  g_qkv);
    cudaGetSymbolAddress((void**)&aout, g_aout);

    cudaFuncSetAttribute(gemm_tc,
                         cudaFuncAttributeMaxDynamicSharedMemorySize,
                         G_SMEM_BYTES);
    cudaFuncSetAttribute(attn_tc,
                         cudaFuncAttributeMaxDynamicSharedMemorySize,
                         A_SMEM_BYTES);

    const int M = BATCH * SEQ;  // 4096

    // 1) QKV projection (mma.sync bf16x3)
    {
        dim3 grid(QKVD / 128, M / 128);
        gemm_tc<<<grid, 256, G_SMEM_BYTES>>>(M, QKVD, DIM, x, W_qkv, b_qkv, qkv);
    }

    // 2) Causal flash attention (mma.sync bf16x3)
    {
        dim3 grid(SEQ / 128, HEADS, BATCH);
        attn_tc<<<grid, 256, A_SMEM_BYTES>>>(qkv, aout);
    }

    // 3) Output projection (mma.sync bf16x3)
    {
        dim3 grid(DIM / 128, M / 128);
        gemm_tc<<<grid, 256, G_SMEM_BYTES>>>(M, DIM, DIM, aout, W_out, b_out, out);
    }
}

// round 7
// speedup vs baseline: 5.5522x; 1.0967x over previous
#include <cuda_runtime.h>
#include <cuda_bf16.h>
#include <math.h>
#include <stdint.h>

// Problem constants
#define BATCH 2
#define SEQ   2048
#define DIM   1024
#define HEADS 16
#define HD    64
#define QKVD  3072   // 3*DIM

// ---------------------------------------------------------------------------
// Global scratch (alloc-free rule). All bf16 hi/lo pairs represent fp32.
// ---------------------------------------------------------------------------
__device__ __nv_bfloat16 g_xh [(size_t)BATCH * SEQ * DIM];
__device__ __nv_bfloat16 g_xl [(size_t)BATCH * SEQ * DIM];
__device__ __nv_bfloat16 g_wqh[(size_t)QKVD * DIM];
__device__ __nv_bfloat16 g_wql[(size_t)QKVD * DIM];
__device__ __nv_bfloat16 g_woh[(size_t)DIM * DIM];
__device__ __nv_bfloat16 g_wol[(size_t)DIM * DIM];
__device__ __nv_bfloat16 g_qkvh[(size_t)BATCH * SEQ * QKVD];
__device__ __nv_bfloat16 g_qkvl[(size_t)BATCH * SEQ * QKVD];
__device__ __nv_bfloat16 g_aoh[(size_t)BATCH * SEQ * DIM];
__device__ __nv_bfloat16 g_aol[(size_t)BATCH * SEQ * DIM];

// ============================================================================
// Helpers (generic PTX, compute_103-safe)
// ============================================================================
__device__ __forceinline__ uint32_t smem_u32(const void* p) {
    uint32_t a;
    asm("{ .reg .u64 t; cvta.to.shared.u64 t, %1; cvt.u32.u64 %0, t; }"
        : "=r"(a) : "l"(p));
    return a;
}
__device__ __forceinline__ void ldsm_x4(uint32_t& r0, uint32_t& r1,
                                        uint32_t& r2, uint32_t& r3,
                                        uint32_t addr) {
    asm volatile("ldmatrix.sync.aligned.m8n8.x4.shared.b16 {%0,%1,%2,%3}, [%4];"
                 : "=r"(r0), "=r"(r1), "=r"(r2), "=r"(r3) : "r"(addr));
}
__device__ __forceinline__ void mma_bf16(float* d, const uint32_t* a,
                                         const uint32_t* b) {
    asm volatile(
        "mma.sync.aligned.m16n8k16.row.col.f32.bf16.bf16.f32 "
        "{%0,%1,%2,%3}, {%4,%5,%6,%7}, {%8,%9}, {%0,%1,%2,%3};"
        : "+f"(d[0]), "+f"(d[1]), "+f"(d[2]), "+f"(d[3])
        : "r"(a[0]), "r"(a[1]), "r"(a[2]), "r"(a[3]), "r"(b[0]), "r"(b[1]));
}
__device__ __forceinline__ void split2(float x, float y,
                                       uint32_t& hi, uint32_t& lo) {
    __nv_bfloat162 h = __floats2bfloat162_rn(x, y);
    float rx = x - __bfloat162float(__low2bfloat16(h));
    float ry = y - __bfloat162float(__high2bfloat16(h));
    __nv_bfloat162 l = __floats2bfloat162_rn(rx, ry);
    hi = *(uint32_t*)&h;
    lo = *(uint32_t*)&l;
}
__device__ __forceinline__ void cp16(uint32_t smem, const void* gmem) {
    asm volatile("cp.async.cg.shared.global [%0], [%1], 16;"
                 :: "r"(smem), "l"(gmem));
}
#define CP_COMMIT() asm volatile("cp.async.commit_group;" ::: "memory")
#define CP_WAIT(n)  asm volatile("cp.async.wait_group %0;" :: "n"(n) : "memory")

// ============================================================================
// split_arr: fp32 -> (bf16 hi, bf16 lo), grid-stride over float4
// ============================================================================
__global__ void split_arr(const float* __restrict__ src,
                          __nv_bfloat16* __restrict__ hi,
                          __nv_bfloat16* __restrict__ lo, int n4) {
    for (int i = blockIdx.x * blockDim.x + threadIdx.x; i < n4;
         i += gridDim.x * blockDim.x) {
        float4 v = ((const float4*)src)[i];
        uint2 h, l;
        split2(v.x, v.y, h.x, l.x);
        split2(v.z, v.w, h.y, l.y);
        ((uint2*)hi)[i] = h;
        ((uint2*)lo)[i] = l;
    }
}

// ============================================================================
// bf16x3 GEMM, pre-split inputs:  C = A @ B^T + bias
//   A: Ah/Al [M][K] bf16, B: Bh/Bl [N_][K] bf16.
//   Output: fp32 C (if C != nullptr) else split bf16 Ch/Cl.
// CTA 128x128, K-chunk 64, triple-buffered cp.async, 8 warps (4m x 2n).
// ============================================================================
#define GKC    64
#define GPITCH 72
#define GTILE_B (128 * GPITCH * 2)        // 18432
#define GSTAGE_B (4 * GTILE_B)            // 73728
#define G_SMEM_BYTES (3 * GSTAGE_B)       // 221184

__global__ __launch_bounds__(256, 1) void gemm_bf16(
    int M, int N_, int K,
    const __nv_bfloat16* __restrict__ Ah, const __nv_bfloat16* __restrict__ Al,
    const __nv_bfloat16* __restrict__ Bh, const __nv_bfloat16* __restrict__ Bl,
    const float* __restrict__ bias,
    float* __restrict__ C,
    __nv_bfloat16* __restrict__ Ch, __nv_bfloat16* __restrict__ Cl)
{
    extern __shared__ __align__(16) char sm[];
    const uint32_t sb0 = smem_u32(sm);

    const int tid = threadIdx.x;
    const int wid = tid >> 5;
    const int lane = tid & 31;
    const int n0 = blockIdx.x * 128;
    const int m0 = blockIdx.y * 128;
    const int warp_m = wid & 3;
    const int warp_n = wid >> 2;

    float acc[2][8][4];
#pragma unroll
    for (int mt = 0; mt < 2; mt++)
#pragma unroll
        for (int nt = 0; nt < 8; nt++)
#pragma unroll
            for (int r = 0; r < 4; r++) acc[mt][nt][r] = 0.0f;

    const int a_row = warp_m * 32 + (lane & 7) + ((lane >> 3) & 1) * 8;
    const int a_kof = ((lane >> 4) & 1) * 8;
    const int b_row = warp_n * 64 + (lane & 7) + ((lane >> 4) & 1) * 8;
    const int b_kof = ((lane >> 3) & 1) * 8;

    const int nchunk = K / GKC;

    auto issue_chunk = [&](int ic, int s) {
        const uint32_t sb = sb0 + (uint32_t)s * GSTAGE_B;
        const int kc = ic * GKC;
#pragma unroll
        for (int i = 0; i < 4; i++) {
            const int id = tid + 256 * i;      // 0..1023
            const int row = id >> 3;
            const int c8 = (id & 7) * 8;
            const uint32_t so = (uint32_t)(row * GPITCH + c8) * 2;
            const size_t ga = (size_t)(m0 + row) * K + kc + c8;
            const size_t gb = (size_t)(n0 + row) * K + kc + c8;
            cp16(sb + so,               Ah + ga);
            cp16(sb + GTILE_B + so,     Al + ga);
            cp16(sb + 2 * GTILE_B + so, Bh + gb);
            cp16(sb + 3 * GTILE_B + so, Bl + gb);
        }
    };

    issue_chunk(0, 0); CP_COMMIT();
    issue_chunk(1, 1); CP_COMMIT();

    for (int ic = 0; ic < nchunk; ic++) {
        CP_WAIT(1);
        __syncthreads();
        if (ic + 2 < nchunk) issue_chunk(ic + 2, (ic + 2) % 3);
        CP_COMMIT();

        const uint32_t sb = sb0 + (uint32_t)(ic % 3) * GSTAGE_B;
        const uint32_t sAh = sb, sAl = sb + GTILE_B;
        const uint32_t sBh = sb + 2 * GTILE_B, sBl = sb + 3 * GTILE_B;

#pragma unroll
        for (int ks = 0; ks < 4; ks++) {
            const int k16 = ks * 16;
            uint32_t ah[2][4], al[2][4];
#pragma unroll
            for (int mt = 0; mt < 2; mt++) {
                const uint32_t aoff =
                    (uint32_t)((a_row + mt * 16) * GPITCH + k16 + a_kof) * 2;
                ldsm_x4(ah[mt][0], ah[mt][1], ah[mt][2], ah[mt][3], sAh + aoff);
                ldsm_x4(al[mt][0], al[mt][1], al[mt][2], al[mt][3], sAl + aoff);
            }
            uint32_t bh[8][2], bl[8][2];
#pragma unroll
            for (int ntp = 0; ntp < 4; ntp++) {
                const uint32_t boff =
                    (uint32_t)((b_row + ntp * 16) * GPITCH + k16 + b_kof) * 2;
                ldsm_x4(bh[2 * ntp][0], bh[2 * ntp][1],
                        bh[2 * ntp + 1][0], bh[2 * ntp + 1][1], sBh + boff);
                ldsm_x4(bl[2 * ntp][0], bl[2 * ntp][1],
                        bl[2 * ntp + 1][0], bl[2 * ntp + 1][1], sBl + boff);
            }
#pragma unroll
            for (int mt = 0; mt < 2; mt++)
#pragma unroll
                for (int nt = 0; nt < 8; nt++) {
                    mma_bf16(acc[mt][nt], ah[mt], bh[nt]);
                    mma_bf16(acc[mt][nt], ah[mt], bl[nt]);
                    mma_bf16(acc[mt][nt], al[mt], bh[nt]);
                }
        }
    }

    // Epilogue
    const int er0 = m0 + warp_m * 32 + (lane >> 2);
    const int ec0 = n0 + warp_n * 64 + (lane & 3) * 2;
#pragma unroll
    for (int mt = 0; mt < 2; mt++) {
#pragma unroll
        for (int nt = 0; nt < 8; nt++) {
            const int col = ec0 + nt * 8;
            const float bx = bias[col], by = bias[col + 1];
            const size_t o0 = (size_t)(er0 + mt * 16) * N_ + col;
            const size_t o1 = (size_t)(er0 + mt * 16 + 8) * N_ + col;
            const float c00 = acc[mt][nt][0] + bx, c01 = acc[mt][nt][1] + by;
            const float c10 = acc[mt][nt][2] + bx, c11 = acc[mt][nt][3] + by;
            if (C) {
                *(float2*)(C + o0) = make_float2(c00, c01);
                *(float2*)(C + o1) = make_float2(c10, c11);
            } else {
                uint32_t h0, l0w, h1, l1w;
                split2(c00, c01, h0, l0w);
                split2(c10, c11, h1, l1w);
                *(uint32_t*)(Ch + o0) = h0;  *(uint32_t*)(Cl + o0) = l0w;
                *(uint32_t*)(Ch + o1) = h1;  *(uint32_t*)(Cl + o1) = l1w;
            }
        }
    }
}

// ============================================================================
// Flash attention, tensor cores, pre-split bf16 qkv inputs.
// Block: 128 q-rows x head, 8 warps (m-split). K-tiles of 64.
// smem: Qh,Ql [128][72]; Kh,Kl,Vth,Vtl [64][72]  (Vt = V transposed [dim][key])
// ============================================================================
#define APITCH 72
#define A_QTILE (128 * APITCH * 2)
#define A_KTILE (64 * APITCH * 2)
#define A_SMEM_BYTES (2 * A_QTILE + 4 * A_KTILE)   // 73728

__global__ __launch_bounds__(256, 1) void attn_tc(
    const __nv_bfloat16* __restrict__ qkvh,
    const __nv_bfloat16* __restrict__ qkvl,
    __nv_bfloat16* __restrict__ aoh,
    __nv_bfloat16* __restrict__ aol)
{
    extern __shared__ __align__(16) char smema[];
    const uint32_t sQh  = smem_u32(smema);
    const uint32_t sQl  = sQh + A_QTILE;
    const uint32_t sKh  = sQl + A_QTILE;
    const uint32_t sKl  = sKh + A_KTILE;
    const uint32_t sVth = sKl + A_KTILE;
    const uint32_t sVtl = sVth + A_KTILE;
    __nv_bfloat16* pVth = (__nv_bfloat16*)(smema + 2 * A_QTILE + 2 * A_KTILE);
    __nv_bfloat16* pVtl = (__nv_bfloat16*)(smema + 2 * A_QTILE + 3 * A_KTILE);

    const int qt = gridDim.x - 1 - blockIdx.x;
    const int h  = blockIdx.y;
    const int b  = blockIdx.z;
    const int tid = threadIdx.x;
    const int wid = tid >> 5;
    const int lane = tid & 31;

    const size_t bN = (size_t)b * SEQ;
    const int qcol = h * HD;
    const int kcol = DIM + h * HD;
    const int vcol = 2 * DIM + h * HD;

    // ---- Q tile via cp.async (128 x 64 bf16, hi+lo) ----
#pragma unroll
    for (int i = 0; i < 4; i++) {
        const int id = tid + 256 * i;
        const int row = id >> 3;
        const int c8 = (id & 7) * 8;
        const uint32_t so = (uint32_t)(row * APITCH + c8) * 2;
        const size_t g = (bN + qt * 128 + row) * QKVD + qcol + c8;
        cp16(sQh + so, qkvh + g);
        cp16(sQl + so, qkvl + g);
    }
    CP_COMMIT();
    CP_WAIT(0);
    __syncthreads();

    // ---- Hoist Q fragments ----
    const int a_row = wid * 16 + (lane & 7) + ((lane >> 3) & 1) * 8;
    const int a_kof = ((lane >> 4) & 1) * 8;
    uint32_t qh[4][4], ql[4][4];
#pragma unroll
    for (int ks = 0; ks < 4; ks++) {
        const uint32_t off = (uint32_t)(a_row * APITCH + ks * 16 + a_kof) * 2;
        ldsm_x4(qh[ks][0], qh[ks][1], qh[ks][2], qh[ks][3], sQh + off);
        ldsm_x4(ql[ks][0], ql[ks][1], ql[ks][2], ql[ks][3], sQl + off);
    }
    __syncthreads();   // Q smem no longer needed as-is (frags held); reuse barrier

    const int b_row = (lane & 7) + ((lane >> 4) & 1) * 8;
    const int b_kof = ((lane >> 3) & 1) * 8;

    float o[8][4];
#pragma unroll
    for (int nt = 0; nt < 8; nt++)
#pragma unroll
        for (int r = 0; r < 4; r++) o[nt][r] = 0.0f;
    float m0 = -1e30f, m1 = -1e30f, l0 = 0.0f, l1 = 0.0f;

    const float scale = 0.125f;
    const int row_lo = qt * 128 + wid * 16 + (lane >> 2);
    const int row_hi = row_lo + 8;
    const int ntiles = (qt + 1) * 2;

    // V transpose thread mapping
    const int vrr = tid >> 2;           // key 0..63
    const int vd0 = (tid & 3) * 16;     // dim 0,16,32,48

    for (int kt = 0; kt < ntiles; kt++) {
        const int kb = kt * 64;

        // ---- K via cp.async ----
#pragma unroll
        for (int i = 0; i < 2; i++) {
            const int id = tid + 256 * i;
            const int row = id >> 3;
            const int c8 = (id & 7) * 8;
            const uint32_t so = (uint32_t)(row * APITCH + c8) * 2;
            const size_t g = (bN + kb + row) * QKVD + kcol + c8;
            cp16(sKh + so, qkvh + g);
            cp16(sKl + so, qkvl + g);
        }
        // ---- V transpose (bf16 scalar copies) ----
        {
            const size_t g = (bN + kb + vrr) * QKVD + vcol + vd0;
            union { uint4 q; __nv_bfloat16 e[8]; } uh0, uh1, ul0, ul1;
            uh0.q = *(const uint4*)(qkvh + g);
            uh1.q = *(const uint4*)(qkvh + g + 8);
            ul0.q = *(const uint4*)(qkvl + g);
            ul1.q = *(const uint4*)(qkvl + g + 8);
#pragma unroll
            for (int e = 0; e < 8; e++) {
                pVth[(vd0 + e) * APITCH + vrr]     = uh0.e[e];
                pVth[(vd0 + 8 + e) * APITCH + vrr] = uh1.e[e];
                pVtl[(vd0 + e) * APITCH + vrr]     = ul0.e[e];
                pVtl[(vd0 + 8 + e) * APITCH + vrr] = ul1.e[e];
            }
        }
        CP_COMMIT();
        CP_WAIT(0);
        __syncthreads();

        // ---- S = Q @ K^T ----
        float s[8][4];
#pragma unroll
        for (int nt = 0; nt < 8; nt++)
#pragma unroll
            for (int r = 0; r < 4; r++) s[nt][r] = 0.0f;

#pragma unroll
        for (int ks = 0; ks < 4; ks++) {
            uint32_t kh[8][2], kl[8][2];
#pragma unroll
            for (int ntp = 0; ntp < 4; ntp++) {
                const uint32_t off =
                    (uint32_t)((ntp * 16 + b_row) * APITCH + ks * 16 + b_kof) * 2;
                ldsm_x4(kh[2 * ntp][0], kh[2 * ntp][1],
                        kh[2 * ntp + 1][0], kh[2 * ntp + 1][1], sKh + off);
                ldsm_x4(kl[2 * ntp][0], kl[2 * ntp][1],
                        kl[2 * ntp + 1][0], kl[2 * ntp + 1][1], sKl + off);
            }
#pragma unroll
            for (int nt = 0; nt < 8; nt++) {
                mma_bf16(s[nt], qh[ks], kh[nt]);
                mma_bf16(s[nt], qh[ks], kl[nt]);
                mma_bf16(s[nt], ql[ks], kh[nt]);
            }
        }

        // ---- Scale + causal mask ----
        const bool full = (kb + 63) <= qt * 128;
        if (full) {
#pragma unroll
            for (int nt = 0; nt < 8; nt++)
#pragma unroll
                for (int r = 0; r < 4; r++) s[nt][r] *= scale;
        } else {
#pragma unroll
            for (int nt = 0; nt < 8; nt++) {
                const int col = kb + nt * 8 + (lane & 3) * 2;
                s[nt][0] = (col     <= row_lo) ? s[nt][0] * scale : -1e30f;
                s[nt][1] = (col + 1 <= row_lo) ? s[nt][1] * scale : -1e30f;
                s[nt][2] = (col     <= row_hi) ? s[nt][2] * scale : -1e30f;
                s[nt][3] = (col + 1 <= row_hi) ? s[nt][3] * scale : -1e30f;
            }
        }

        // ---- Online softmax ----
        float tm0 = -1e30f, tm1 = -1e30f;
#pragma unroll
        for (int nt = 0; nt < 8; nt++) {
            tm0 = fmaxf(tm0, fmaxf(s[nt][0], s[nt][1]));
            tm1 = fmaxf(tm1, fmaxf(s[nt][2], s[nt][3]));
        }
        tm0 = fmaxf(tm0, __shfl_xor_sync(0xffffffffu, tm0, 1));
        tm0 = fmaxf(tm0, __shfl_xor_sync(0xffffffffu, tm0, 2));
        tm1 = fmaxf(tm1, __shfl_xor_sync(0xffffffffu, tm1, 1));
        tm1 = fmaxf(tm1, __shfl_xor_sync(0xffffffffu, tm1, 2));

        const float nm0 = fmaxf(m0, tm0);
        const float nm1 = fmaxf(m1, tm1);
        const float corr0 = __expf(m0 - nm0);
        const float corr1 = __expf(m1 - nm1);

        float ps0 = 0.0f, ps1 = 0.0f;
#pragma unroll
        for (int nt = 0; nt < 8; nt++) {
            s[nt][0] = __expf(s[nt][0] - nm0); ps0 += s[nt][0];
            s[nt][1] = __expf(s[nt][1] - nm0); ps0 += s[nt][1];
            s[nt][2] = __expf(s[nt][2] - nm1); ps1 += s[nt][2];
            s[nt][3] = __expf(s[nt][3] - nm1); ps1 += s[nt][3];
        }
        ps0 += __shfl_xor_sync(0xffffffffu, ps0, 1);
        ps0 += __shfl_xor_sync(0xffffffffu, ps0, 2);
        ps1 += __shfl_xor_sync(0xffffffffu, ps1, 1);
        ps1 += __shfl_xor_sync(0xffffffffu, ps1, 2);

        l0 = l0 * corr0 + ps0; m0 = nm0;
        l1 = l1 * corr1 + ps1; m1 = nm1;
#pragma unroll
        for (int nt = 0; nt < 8; nt++) {
            o[nt][0] *= corr0; o[nt][1] *= corr0;
            o[nt][2] *= corr1; o[nt][3] *= corr1;
        }

        // ---- O += P @ V (register repack, split Ph/Pl) ----
#pragma unroll
        for (int ks = 0; ks < 4; ks++) {
            uint32_t ah[4], al[4];
            const int j = 2 * ks;
            split2(s[j][0],     s[j][1],     ah[0], al[0]);
            split2(s[j][2],     s[j][3],     ah[1], al[1]);
            split2(s[j + 1][0], s[j + 1][1], ah[2], al[2]);
            split2(s[j + 1][2], s[j + 1][3], ah[3], al[3]);

            uint32_t vh[8][2], vl[8][2];
#pragma unroll
            for (int ntp = 0; ntp < 4; ntp++) {
                const uint32_t off =
                    (uint32_t)((ntp * 16 + b_row) * APITCH + ks * 16 + b_kof) * 2;
                ldsm_x4(vh[2 * ntp][0], vh[2 * ntp][1],
                        vh[2 * ntp + 1][0], vh[2 * ntp + 1][1], sVth + off);
                ldsm_x4(vl[2 * ntp][0], vl[2 * ntp][1],
                        vl[2 * ntp + 1][0], vl[2 * ntp + 1][1], sVtl + off);
            }
#pragma unroll
            for (int nt = 0; nt < 8; nt++) {
                mma_bf16(o[nt], ah, vh[nt]);
                mma_bf16(o[nt], ah, vl[nt]);
                mma_bf16(o[nt], al, vh[nt]);
            }
        }
        __syncthreads();
    }

    // ---- Epilogue: normalize + split-store to aoh/aol ----
    const float inv0 = 1.0f / l0;
    const float inv1 = 1.0f / l1;
#pragma unroll
    for (int nt = 0; nt < 8; nt++) {
        const int col = h * HD + nt * 8 + (lane & 3) * 2;
        const size_t o0 = (bN + row_lo) * DIM + col;
        const size_t o1 = (bN + row_hi) * DIM + col;
        uint32_t h0, l0w, h1, l1w;
        split2(o[nt][0] * inv0, o[nt][1] * inv0, h0, l0w);
        split2(o[nt][2] * inv1, o[nt][3] * inv1, h1, l1w);
        *(uint32_t*)(aoh + o0) = h0;  *(uint32_t*)(aol + o0) = l0w;
        *(uint32_t*)(aoh + o1) = h1;  *(uint32_t*)(aol + o1) = l1w;
    }
}

// ---------------------------------------------------------------------------
extern "C" void kernel_launch(void* const* d_in, const int* in_sizes, int n_in,
                              void* d_out, int out_size)
{
    const float* x     = (const float*)d_in[0];
    const float* W_qkv = (const float*)d_in[1];
    const float* b_qkv = (const float*)d_in[2];
    const float* W_out = (const float*)d_in[3];
    const float* b_out = (const float*)d_in[4];
    float* out = (float*)d_out;

    __nv_bfloat16 *xh, *xl, *wqh, *wql, *woh, *wol, *qkvh, *qkvl, *aoh, *aol;
    cudaGetSymbolAddress((void**)&xh,  g_xh);   cudaGetSymbolAddress((void**)&xl,  g_xl);
    cudaGetSymbolAddress((void**)&wqh, g_wqh);  cudaGetSymbolAddress((void**)&wql, g_wql);
    cudaGetSymbolAddress((void**)&woh, g_woh);  cudaGetSymbolAddress((void**)&wol, g_wol);
    cudaGetSymbolAddress((void**)&qkvh, g_qkvh); cudaGetSymbolAddress((void**)&qkvl, g_qkvl);
    cudaGetSymbolAddress((void**)&aoh, g_aoh);  cudaGetSymbolAddress((void**)&aol, g_aol);

    cudaFuncSetAttribute(gemm_bf16,
                         cudaFuncAttributeMaxDynamicSharedMemorySize, G_SMEM_BYTES);
    cudaFuncSetAttribute(attn_tc,
                         cudaFuncAttributeMaxDynamicSharedMemorySize, A_SMEM_BYTES);

    const int M = BATCH * SEQ;  // 4096

    // 0) Pre-split inputs
    split_arr<<<1024, 256>>>(x,     xh,  xl,  M * DIM / 4);
    split_arr<<<1024, 256>>>(W_qkv, wqh, wql, QKVD * DIM / 4);
    split_arr<<<512,  256>>>(W_out, woh, wol, DIM * DIM / 4);

    // 1) QKV projection -> split bf16 qkv
    {
        dim3 grid(QKVD / 128, M / 128);
        gemm_bf16<<<grid, 256, G_SMEM_BYTES>>>(M, QKVD, DIM, xh, xl, wqh, wql,
                                               b_qkv, nullptr, qkvh, qkvl);
    }
    // 2) Attention -> split bf16 aout
    {
        dim3 grid(SEQ / 128, HEADS, BATCH);
        attn_tc<<<grid, 256, A_SMEM_BYTES>>>(qkvh, qkvl, aoh, aol);
    }
    // 3) Output projection -> fp32 out
    {
        dim3 grid(DIM / 128, M / 128);
        gemm_bf16<<<grid, 256, G_SMEM_BYTES>>>(M, DIM, DIM, aoh, aol, woh, wol,
                                               b_out, out, nullptr, nullptr);
    }
}

// round 8
// speedup vs baseline: 5.7142x; 1.0292x over previous
#include <cuda_runtime.h>
#include <cuda_bf16.h>
#include <math.h>
#include <stdint.h>

// Problem constants
#define BATCH 2
#define SEQ   2048
#define DIM   1024
#define HEADS 16
#define HD    64
#define QKVD  3072   // 3*DIM

// ---------------------------------------------------------------------------
// Global scratch (alloc-free rule). All bf16 hi/lo pairs represent fp32.
// ---------------------------------------------------------------------------
__device__ __nv_bfloat16 g_xh [(size_t)BATCH * SEQ * DIM];
__device__ __nv_bfloat16 g_xl [(size_t)BATCH * SEQ * DIM];
__device__ __nv_bfloat16 g_wqh[(size_t)QKVD * DIM];
__device__ __nv_bfloat16 g_wql[(size_t)QKVD * DIM];
__device__ __nv_bfloat16 g_woh[(size_t)DIM * DIM];
__device__ __nv_bfloat16 g_wol[(size_t)DIM * DIM];
__device__ __nv_bfloat16 g_qkvh[(size_t)BATCH * SEQ * QKVD];
__device__ __nv_bfloat16 g_qkvl[(size_t)BATCH * SEQ * QKVD];
__device__ __nv_bfloat16 g_aoh[(size_t)BATCH * SEQ * DIM];
__device__ __nv_bfloat16 g_aol[(size_t)BATCH * SEQ * DIM];

// ============================================================================
// Helpers (generic PTX, compute_103-safe)
// ============================================================================
__device__ __forceinline__ uint32_t smem_u32(const void* p) {
    uint32_t a;
    asm("{ .reg .u64 t; cvta.to.shared.u64 t, %1; cvt.u32.u64 %0, t; }"
        : "=r"(a) : "l"(p));
    return a;
}
__device__ __forceinline__ void ldsm_x4(uint32_t& r0, uint32_t& r1,
                                        uint32_t& r2, uint32_t& r3,
                                        uint32_t addr) {
    asm volatile("ldmatrix.sync.aligned.m8n8.x4.shared.b16 {%0,%1,%2,%3}, [%4];"
                 : "=r"(r0), "=r"(r1), "=r"(r2), "=r"(r3) : "r"(addr));
}
__device__ __forceinline__ void mma_bf16(float* d, const uint32_t* a,
                                         const uint32_t* b) {
    asm volatile(
        "mma.sync.aligned.m16n8k16.row.col.f32.bf16.bf16.f32 "
        "{%0,%1,%2,%3}, {%4,%5,%6,%7}, {%8,%9}, {%0,%1,%2,%3};"
        : "+f"(d[0]), "+f"(d[1]), "+f"(d[2]), "+f"(d[3])
        : "r"(a[0]), "r"(a[1]), "r"(a[2]), "r"(a[3]), "r"(b[0]), "r"(b[1]));
}
__device__ __forceinline__ void split2(float x, float y,
                                       uint32_t& hi, uint32_t& lo) {
    __nv_bfloat162 h = __floats2bfloat162_rn(x, y);
    float rx = x - __bfloat162float(__low2bfloat16(h));
    float ry = y - __bfloat162float(__high2bfloat16(h));
    __nv_bfloat162 l = __floats2bfloat162_rn(rx, ry);
    hi = *(uint32_t*)&h;
    lo = *(uint32_t*)&l;
}
__device__ __forceinline__ void cp16(uint32_t smem, const void* gmem) {
    asm volatile("cp.async.cg.shared.global [%0], [%1], 16;"
                 :: "r"(smem), "l"(gmem));
}
#define CP_COMMIT() asm volatile("cp.async.commit_group;" ::: "memory")
#define CP_WAIT(n)  asm volatile("cp.async.wait_group %0;" :: "n"(n) : "memory")

// ============================================================================
// split_arr: fp32 -> (bf16 hi, bf16 lo), grid-stride over float4
// ============================================================================
__global__ void split_arr(const float* __restrict__ src,
                          __nv_bfloat16* __restrict__ hi,
                          __nv_bfloat16* __restrict__ lo, int n4) {
    for (int i = blockIdx.x * blockDim.x + threadIdx.x; i < n4;
         i += gridDim.x * blockDim.x) {
        float4 v = ((const float4*)src)[i];
        uint2 h, l;
        split2(v.x, v.y, h.x, l.x);
        split2(v.z, v.w, h.y, l.y);
        ((uint2*)hi)[i] = h;
        ((uint2*)lo)[i] = l;
    }
}

// ============================================================================
// bf16x3 GEMM, pre-split inputs:  C = A @ B^T + bias
// CTA tile 256x128, K-chunk 64, 2-stage cp.async, 8 warps (4m x 2n),
// warp tile 64x64 (0.167 LDSM per MMA -> tensor-bound).
// ============================================================================
#define GKC    64
#define GPITCH 72
#define GA_TILE (256 * GPITCH * 2)        // 36864 B (one of hi/lo)
#define GB_TILE (128 * GPITCH * 2)        // 18432 B
#define GSTAGE_B (2 * GA_TILE + 2 * GB_TILE)   // 110592 B
#define G_SMEM_BYTES (2 * GSTAGE_B)            // 221184 B

__global__ __launch_bounds__(256, 1) void gemm_bf16(
    int M, int N_, int K,
    const __nv_bfloat16* __restrict__ Ah, const __nv_bfloat16* __restrict__ Al,
    const __nv_bfloat16* __restrict__ Bh, const __nv_bfloat16* __restrict__ Bl,
    const float* __restrict__ bias,
    float* __restrict__ C,
    __nv_bfloat16* __restrict__ Ch, __nv_bfloat16* __restrict__ Cl)
{
    extern __shared__ __align__(16) char sm[];
    const uint32_t sb0 = smem_u32(sm);

    const int tid = threadIdx.x;
    const int wid = tid >> 5;
    const int lane = tid & 31;
    const int n0 = blockIdx.x * 128;
    const int m0 = blockIdx.y * 256;
    const int warp_m = wid & 3;         // 64-row slice
    const int warp_n = wid >> 2;        // 64-col slice

    float acc[4][8][4];
#pragma unroll
    for (int mt = 0; mt < 4; mt++)
#pragma unroll
        for (int nt = 0; nt < 8; nt++)
#pragma unroll
            for (int r = 0; r < 4; r++) acc[mt][nt][r] = 0.0f;

    const int a_row = warp_m * 64 + (lane & 7) + ((lane >> 3) & 1) * 8;
    const int a_kof = ((lane >> 4) & 1) * 8;
    const int b_row = warp_n * 64 + (lane & 7) + ((lane >> 4) & 1) * 8;
    const int b_kof = ((lane >> 3) & 1) * 8;

    const int nchunk = K / GKC;

    auto issue_chunk = [&](int ic, int s) {
        const uint32_t sb = sb0 + (uint32_t)s * GSTAGE_B;
        const int kc = ic * GKC;
        // A: 256 rows x 8 col-groups = 2048 segs -> 8 per thread (hi+lo pairs)
#pragma unroll
        for (int i = 0; i < 8; i++) {
            const int id = tid + 256 * i;
            const int row = id >> 3;
            const int c8 = (id & 7) * 8;
            const uint32_t so = (uint32_t)(row * GPITCH + c8) * 2;
            const size_t ga = (size_t)(m0 + row) * K + kc + c8;
            cp16(sb + so,           Ah + ga);
            cp16(sb + GA_TILE + so, Al + ga);
        }
        // B: 128 rows x 8 col-groups = 1024 segs -> 4 per thread
#pragma unroll
        for (int i = 0; i < 4; i++) {
            const int id = tid + 256 * i;
            const int row = id >> 3;
            const int c8 = (id & 7) * 8;
            const uint32_t so = (uint32_t)(row * GPITCH + c8) * 2;
            const size_t gb = (size_t)(n0 + row) * K + kc + c8;
            cp16(sb + 2 * GA_TILE + so,           Bh + gb);
            cp16(sb + 2 * GA_TILE + GB_TILE + so, Bl + gb);
        }
    };

    issue_chunk(0, 0); CP_COMMIT();

    for (int ic = 0; ic < nchunk; ic++) {
        if (ic + 1 < nchunk) {
            issue_chunk(ic + 1, (ic + 1) & 1); CP_COMMIT();
            CP_WAIT(1);
        } else {
            CP_WAIT(0);
        }
        __syncthreads();

        const uint32_t sb  = sb0 + (uint32_t)(ic & 1) * GSTAGE_B;
        const uint32_t sAh = sb;
        const uint32_t sAl = sb + GA_TILE;
        const uint32_t sBh = sb + 2 * GA_TILE;
        const uint32_t sBl = sb + 2 * GA_TILE + GB_TILE;

#pragma unroll
        for (int ks = 0; ks < 4; ks++) {
            const int k16 = ks * 16;
            uint32_t ah[4][4], al[4][4];
#pragma unroll
            for (int mt = 0; mt < 4; mt++) {
                const uint32_t aoff =
                    (uint32_t)((a_row + mt * 16) * GPITCH + k16 + a_kof) * 2;
                ldsm_x4(ah[mt][0], ah[mt][1], ah[mt][2], ah[mt][3], sAh + aoff);
                ldsm_x4(al[mt][0], al[mt][1], al[mt][2], al[mt][3], sAl + aoff);
            }
            uint32_t bh[8][2], bl[8][2];
#pragma unroll
            for (int ntp = 0; ntp < 4; ntp++) {
                const uint32_t boff =
                    (uint32_t)((b_row + ntp * 16) * GPITCH + k16 + b_kof) * 2;
                ldsm_x4(bh[2 * ntp][0], bh[2 * ntp][1],
                        bh[2 * ntp + 1][0], bh[2 * ntp + 1][1], sBh + boff);
                ldsm_x4(bl[2 * ntp][0], bl[2 * ntp][1],
                        bl[2 * ntp + 1][0], bl[2 * ntp + 1][1], sBl + boff);
            }
#pragma unroll
            for (int mt = 0; mt < 4; mt++)
#pragma unroll
                for (int nt = 0; nt < 8; nt++) {
                    mma_bf16(acc[mt][nt], ah[mt], bh[nt]);
                    mma_bf16(acc[mt][nt], ah[mt], bl[nt]);
                    mma_bf16(acc[mt][nt], al[mt], bh[nt]);
                }
        }
        __syncthreads();
    }

    // Epilogue
    const int er0 = m0 + warp_m * 64 + (lane >> 2);
    const int ec0 = n0 + warp_n * 64 + (lane & 3) * 2;
#pragma unroll
    for (int mt = 0; mt < 4; mt++) {
#pragma unroll
        for (int nt = 0; nt < 8; nt++) {
            const int col = ec0 + nt * 8;
            const float bx = bias[col], by = bias[col + 1];
            const size_t o0 = (size_t)(er0 + mt * 16) * N_ + col;
            const size_t o1 = (size_t)(er0 + mt * 16 + 8) * N_ + col;
            const float c00 = acc[mt][nt][0] + bx, c01 = acc[mt][nt][1] + by;
            const float c10 = acc[mt][nt][2] + bx, c11 = acc[mt][nt][3] + by;
            if (C) {
                *(float2*)(C + o0) = make_float2(c00, c01);
                *(float2*)(C + o1) = make_float2(c10, c11);
            } else {
                uint32_t h0, l0w, h1, l1w;
                split2(c00, c01, h0, l0w);
                split2(c10, c11, h1, l1w);
                *(uint32_t*)(Ch + o0) = h0;  *(uint32_t*)(Cl + o0) = l0w;
                *(uint32_t*)(Ch + o1) = h1;  *(uint32_t*)(Cl + o1) = l1w;
            }
        }
    }
}

// ============================================================================
// Flash attention, tensor cores, pre-split bf16 qkv inputs (unchanged R7).
// ============================================================================
#define APITCH 72
#define A_QTILE (128 * APITCH * 2)
#define A_KTILE (64 * APITCH * 2)
#define A_SMEM_BYTES (2 * A_QTILE + 4 * A_KTILE)   // 73728

__global__ __launch_bounds__(256, 1) void attn_tc(
    const __nv_bfloat16* __restrict__ qkvh,
    const __nv_bfloat16* __restrict__ qkvl,
    __nv_bfloat16* __restrict__ aoh,
    __nv_bfloat16* __restrict__ aol)
{
    extern __shared__ __align__(16) char smema[];
    const uint32_t sQh  = smem_u32(smema);
    const uint32_t sQl  = sQh + A_QTILE;
    const uint32_t sKh  = sQl + A_QTILE;
    const uint32_t sKl  = sKh + A_KTILE;
    const uint32_t sVth = sKl + A_KTILE;
    const uint32_t sVtl = sVth + A_KTILE;
    __nv_bfloat16* pVth = (__nv_bfloat16*)(smema + 2 * A_QTILE + 2 * A_KTILE);
    __nv_bfloat16* pVtl = (__nv_bfloat16*)(smema + 2 * A_QTILE + 3 * A_KTILE);

    const int qt = gridDim.x - 1 - blockIdx.x;
    const int h  = blockIdx.y;
    const int b  = blockIdx.z;
    const int tid = threadIdx.x;
    const int wid = tid >> 5;
    const int lane = tid & 31;

    const size_t bN = (size_t)b * SEQ;
    const int qcol = h * HD;
    const int kcol = DIM + h * HD;
    const int vcol = 2 * DIM + h * HD;

#pragma unroll
    for (int i = 0; i < 4; i++) {
        const int id = tid + 256 * i;
        const int row = id >> 3;
        const int c8 = (id & 7) * 8;
        const uint32_t so = (uint32_t)(row * APITCH + c8) * 2;
        const size_t g = (bN + qt * 128 + row) * QKVD + qcol + c8;
        cp16(sQh + so, qkvh + g);
        cp16(sQl + so, qkvl + g);
    }
    CP_COMMIT();
    CP_WAIT(0);
    __syncthreads();

    const int a_row = wid * 16 + (lane & 7) + ((lane >> 3) & 1) * 8;
    const int a_kof = ((lane >> 4) & 1) * 8;
    uint32_t qh[4][4], ql[4][4];
#pragma unroll
    for (int ks = 0; ks < 4; ks++) {
        const uint32_t off = (uint32_t)(a_row * APITCH + ks * 16 + a_kof) * 2;
        ldsm_x4(qh[ks][0], qh[ks][1], qh[ks][2], qh[ks][3], sQh + off);
        ldsm_x4(ql[ks][0], ql[ks][1], ql[ks][2], ql[ks][3], sQl + off);
    }
    __syncthreads();

    const int b_row = (lane & 7) + ((lane >> 4) & 1) * 8;
    const int b_kof = ((lane >> 3) & 1) * 8;

    float o[8][4];
#pragma unroll
    for (int nt = 0; nt < 8; nt++)
#pragma unroll
        for (int r = 0; r < 4; r++) o[nt][r] = 0.0f;
    float m0 = -1e30f, m1 = -1e30f, l0 = 0.0f, l1 = 0.0f;

    const float scale = 0.125f;
    const int row_lo = qt * 128 + wid * 16 + (lane >> 2);
    const int row_hi = row_lo + 8;
    const int ntiles = (qt + 1) * 2;

    const int vrr = tid >> 2;
    const int vd0 = (tid & 3) * 16;

    for (int kt = 0; kt < ntiles; kt++) {
        const int kb = kt * 64;

#pragma unroll
        for (int i = 0; i < 2; i++) {
            const int id = tid + 256 * i;
            const int row = id >> 3;
            const int c8 = (id & 7) * 8;
            const uint32_t so = (uint32_t)(row * APITCH + c8) * 2;
            const size_t g = (bN + kb + row) * QKVD + kcol + c8;
            cp16(sKh + so, qkvh + g);
            cp16(sKl + so, qkvl + g);
        }
        {
            const size_t g = (bN + kb + vrr) * QKVD + vcol + vd0;
            union { uint4 q; __nv_bfloat16 e[8]; } uh0, uh1, ul0, ul1;
            uh0.q = *(const uint4*)(qkvh + g);
            uh1.q = *(const uint4*)(qkvh + g + 8);
            ul0.q = *(const uint4*)(qkvl + g);
            ul1.q = *(const uint4*)(qkvl + g + 8);
#pragma unroll
            for (int e = 0; e < 8; e++) {
                pVth[(vd0 + e) * APITCH + vrr]     = uh0.e[e];
                pVth[(vd0 + 8 + e) * APITCH + vrr] = uh1.e[e];
                pVtl[(vd0 + e) * APITCH + vrr]     = ul0.e[e];
                pVtl[(vd0 + 8 + e) * APITCH + vrr] = ul1.e[e];
            }
        }
        CP_COMMIT();
        CP_WAIT(0);
        __syncthreads();

        float s[8][4];
#pragma unroll
        for (int nt = 0; nt < 8; nt++)
#pragma unroll
            for (int r = 0; r < 4; r++) s[nt][r] = 0.0f;

#pragma unroll
        for (int ks = 0; ks < 4; ks++) {
            uint32_t kh[8][2], kl[8][2];
#pragma unroll
            for (int ntp = 0; ntp < 4; ntp++) {
                const uint32_t off =
                    (uint32_t)((ntp * 16 + b_row) * APITCH + ks * 16 + b_kof) * 2;
                ldsm_x4(kh[2 * ntp][0], kh[2 * ntp][1],
                        kh[2 * ntp + 1][0], kh[2 * ntp + 1][1], sKh + off);
                ldsm_x4(kl[2 * ntp][0], kl[2 * ntp][1],
                        kl[2 * ntp + 1][0], kl[2 * ntp + 1][1], sKl + off);
            }
#pragma unroll
            for (int nt = 0; nt < 8; nt++) {
                mma_bf16(s[nt], qh[ks], kh[nt]);
                mma_bf16(s[nt], qh[ks], kl[nt]);
                mma_bf16(s[nt], ql[ks], kh[nt]);
            }
        }

        const bool full = (kb + 63) <= qt * 128;
        if (full) {
#pragma unroll
            for (int nt = 0; nt < 8; nt++)
#pragma unroll
                for (int r = 0; r < 4; r++) s[nt][r] *= scale;
        } else {
#pragma unroll
            for (int nt = 0; nt < 8; nt++) {
                const int col = kb + nt * 8 + (lane & 3) * 2;
                s[nt][0] = (col     <= row_lo) ? s[nt][0] * scale : -1e30f;
                s[nt][1] = (col + 1 <= row_lo) ? s[nt][1] * scale : -1e30f;
                s[nt][2] = (col     <= row_hi) ? s[nt][2] * scale : -1e30f;
                s[nt][3] = (col + 1 <= row_hi) ? s[nt][3] * scale : -1e30f;
            }
        }

        float tm0 = -1e30f, tm1 = -1e30f;
#pragma unroll
        for (int nt = 0; nt < 8; nt++) {
            tm0 = fmaxf(tm0, fmaxf(s[nt][0], s[nt][1]));
            tm1 = fmaxf(tm1, fmaxf(s[nt][2], s[nt][3]));
        }
        tm0 = fmaxf(tm0, __shfl_xor_sync(0xffffffffu, tm0, 1));
        tm0 = fmaxf(tm0, __shfl_xor_sync(0xffffffffu, tm0, 2));
        tm1 = fmaxf(tm1, __shfl_xor_sync(0xffffffffu, tm1, 1));
        tm1 = fmaxf(tm1, __shfl_xor_sync(0xffffffffu, tm1, 2));

        const float nm0 = fmaxf(m0, tm0);
        const float nm1 = fmaxf(m1, tm1);
        const float corr0 = __expf(m0 - nm0);
        const float corr1 = __expf(m1 - nm1);

        float ps0 = 0.0f, ps1 = 0.0f;
#pragma unroll
        for (int nt = 0; nt < 8; nt++) {
            s[nt][0] = __expf(s[nt][0] - nm0); ps0 += s[nt][0];
            s[nt][1] = __expf(s[nt][1] - nm0); ps0 += s[nt][1];
            s[nt][2] = __expf(s[nt][2] - nm1); ps1 += s[nt][2];
            s[nt][3] = __expf(s[nt][3] - nm1); ps1 += s[nt][3];
        }
        ps0 += __shfl_xor_sync(0xffffffffu, ps0, 1);
        ps0 += __shfl_xor_sync(0xffffffffu, ps0, 2);
        ps1 += __shfl_xor_sync(0xffffffffu, ps1, 1);
        ps1 += __shfl_xor_sync(0xffffffffu, ps1, 2);

        l0 = l0 * corr0 + ps0; m0 = nm0;
        l1 = l1 * corr1 + ps1; m1 = nm1;
#pragma unroll
        for (int nt = 0; nt < 8; nt++) {
            o[nt][0] *= corr0; o[nt][1] *= corr0;
            o[nt][2] *= corr1; o[nt][3] *= corr1;
        }

#pragma unroll
        for (int ks = 0; ks < 4; ks++) {
            uint32_t ah[4], al[4];
            const int j = 2 * ks;
            split2(s[j][0],     s[j][1],     ah[0], al[0]);
            split2(s[j][2],     s[j][3],     ah[1], al[1]);
            split2(s[j + 1][0], s[j + 1][1], ah[2], al[2]);
            split2(s[j + 1][2], s[j + 1][3], ah[3], al[3]);

            uint32_t vh[8][2], vl[8][2];
#pragma unroll
            for (int ntp = 0; ntp < 4; ntp++) {
                const uint32_t off =
                    (uint32_t)((ntp * 16 + b_row) * APITCH + ks * 16 + b_kof) * 2;
                ldsm_x4(vh[2 * ntp][0], vh[2 * ntp][1],
                        vh[2 * ntp + 1][0], vh[2 * ntp + 1][1], sVth + off);
                ldsm_x4(vl[2 * ntp][0], vl[2 * ntp][1],
                        vl[2 * ntp + 1][0], vl[2 * ntp + 1][1], sVtl + off);
            }
#pragma unroll
            for (int nt = 0; nt < 8; nt++) {
                mma_bf16(o[nt], ah, vh[nt]);
                mma_bf16(o[nt], ah, vl[nt]);
                mma_bf16(o[nt], al, vh[nt]);
            }
        }
        __syncthreads();
    }

    const float inv0 = 1.0f / l0;
    const float inv1 = 1.0f / l1;
#pragma unroll
    for (int nt = 0; nt < 8; nt++) {
        const int col = h * HD + nt * 8 + (lane & 3) * 2;
        const size_t o0 = (bN + row_lo) * DIM + col;
        const size_t o1 = (bN + row_hi) * DIM + col;
        uint32_t h0, l0w, h1, l1w;
        split2(o[nt][0] * inv0, o[nt][1] * inv0, h0, l0w);
        split2(o[nt][2] * inv1, o[nt][3] * inv1, h1, l1w);
        *(uint32_t*)(aoh + o0) = h0;  *(uint32_t*)(aol + o0) = l0w;
        *(uint32_t*)(aoh + o1) = h1;  *(uint32_t*)(aol + o1) = l1w;
    }
}

// ---------------------------------------------------------------------------
extern "C" void kernel_launch(void* const* d_in, const int* in_sizes, int n_in,
                              void* d_out, int out_size)
{
    const float* x     = (const float*)d_in[0];
    const float* W_qkv = (const float*)d_in[1];
    const float* b_qkv = (const float*)d_in[2];
    const float* W_out = (const float*)d_in[3];
    const float* b_out = (const float*)d_in[4];
    float* out = (float*)d_out;

    __nv_bfloat16 *xh, *xl, *wqh, *wql, *woh, *wol, *qkvh, *qkvl, *aoh, *aol;
    cudaGetSymbolAddress((void**)&xh,  g_xh);   cudaGetSymbolAddress((void**)&xl,  g_xl);
    cudaGetSymbolAddress((void**)&wqh, g_wqh);  cudaGetSymbolAddress((void**)&wql, g_wql);
    cudaGetSymbolAddress((void**)&woh, g_woh);  cudaGetSymbolAddress((void**)&wol, g_wol);
    cudaGetSymbolAddress((void**)&qkvh, g_qkvh); cudaGetSymbolAddress((void**)&qkvl, g_qkvl);
    cudaGetSymbolAddress((void**)&aoh, g_aoh);  cudaGetSymbolAddress((void**)&aol, g_aol);

    cudaFuncSetAttribute(gemm_bf16,
                         cudaFuncAttributeMaxDynamicSharedMemorySize, G_SMEM_BYTES);
    cudaFuncSetAttribute(attn_tc,
                         cudaFuncAttributeMaxDynamicSharedMemorySize, A_SMEM_BYTES);

    const int M = BATCH * SEQ;  // 4096

    // 0) Pre-split inputs
    split_arr<<<1024, 256>>>(x,     xh,  xl,  M * DIM / 4);
    split_arr<<<1024, 256>>>(W_qkv, wqh, wql, QKVD * DIM / 4);
    split_arr<<<512,  256>>>(W_out, woh, wol, DIM * DIM / 4);

    // 1) QKV projection -> split bf16 qkv
    {
        dim3 grid(QKVD / 128, M / 256);
        gemm_bf16<<<grid, 256, G_SMEM_BYTES>>>(M, QKVD, DIM, xh, xl, wqh, wql,
                                               b_qkv, nullptr, qkvh, qkvl);
    }
    // 2) Attention -> split bf16 aout
    {
        dim3 grid(SEQ / 128, HEADS, BATCH);
        attn_tc<<<grid, 256, A_SMEM_BYTES>>>(qkvh, qkvl, aoh, aol);
    }
    // 3) Output projection -> fp32 out
    {
        dim3 grid(DIM / 128, M / 256);
        gemm_bf16<<<grid, 256, G_SMEM_BYTES>>>(M, DIM, DIM, aoh, aol, woh, wol,
                                               b_out, out, nullptr, nullptr);
    }
}